// round 13
// baseline (speedup 1.0000x reference)
#include <cuda_runtime.h>
#include <cuda_bf16.h>
#include <math.h>
#include <stdint.h>

// ---------------- problem constants ----------------
#define BATCH   2
#define LSEQ    1024
#define DMODEL  1024
#define DINNER  2048
#define DSTATE  16
#define DTRANK  64
#define KCONV   4
#define TOK     (BATCH*LSEQ)        // 2048 tokens
#define XDBL_N  96
#define XPAD    128                 // padded xdbl stride
#define EPS     1e-5f
#define LOG2E   1.44269504088896f

#define NCHUNK  32
#define CLEN    (LSEQ/NCHUNK)       // 32
#define DN      (DINNER*DSTATE)     // 32768
#define XKSPLIT 8                   // x_proj K splits (MMA)

// ---------------- scratch ----------------
__device__ __align__(16) __nv_bfloat16 g_hb    [TOK * DMODEL];       // rmsnorm out
__device__ __align__(16) __nv_bfloat16 g_yb    [TOK * DINNER];       // scan out
__device__ __align__(16) __nv_bfloat16 g_wint  [2*DINNER * DMODEL];  // W_in^T
__device__ __align__(16) __nv_bfloat16 g_woutt [DMODEL * DINNER];    // W_out^T
__device__ __align__(16) __nv_bfloat16 g_wxt   [XPAD * DINNER];      // W_x^T padded
__device__ __align__(16) __nv_bfloat16 g_xresb [TOK * 2 * DINNER];   // in_proj out
__device__ __align__(16) __nv_bfloat16 g_xcb   [TOK * DINNER];       // conv+silu out
__device__ __align__(16) __nv_bfloat16 g_deltab[TOK * DINNER];       // softplus(dt)
__device__ __align__(16) float g_xdbl [TOK * XPAD];                  // B/C cols used
__device__ __align__(16) float g_xpf  [XKSPLIT * TOK * XPAD];        // x_proj partials
__device__ __align__(16) float g_S    [BATCH * NCHUNK * DN];
__device__ __align__(16) float g_P    [BATCH * NCHUNK * DN];
__device__ __align__(16) float g_SI   [BATCH * NCHUNK * DN];

// ---------------- helpers ----------------
__device__ __forceinline__ float silu_f(float x) {
    return x / (1.f + __expf(-x));
}
__device__ __forceinline__ float ex2f(float x) {
    float r;
    asm("ex2.approx.f32 %0, %1;" : "=f"(r) : "f"(x));
    return r;
}
__device__ __forceinline__ void cp16(uint32_t smem, const void* g) {
    asm volatile("cp.async.cg.shared.global [%0], [%1], 16;\n" :: "r"(smem), "l"(g));
}
__device__ __forceinline__ void mma_bf16(float c[4],
    uint32_t a0, uint32_t a1, uint32_t a2, uint32_t a3,
    uint32_t b0, uint32_t b1) {
    asm volatile(
        "mma.sync.aligned.m16n8k16.row.col.f32.bf16.bf16.f32 "
        "{%0,%1,%2,%3}, {%4,%5,%6,%7}, {%8,%9}, {%0,%1,%2,%3};"
        : "+f"(c[0]), "+f"(c[1]), "+f"(c[2]), "+f"(c[3])
        : "r"(a0), "r"(a1), "r"(a2), "r"(a3), "r"(b0), "r"(b1));
}
__device__ __forceinline__ void ldmx4(uint32_t r[4], uint32_t addr) {
    asm volatile(
        "ldmatrix.sync.aligned.m8n8.x4.shared.b16 {%0,%1,%2,%3}, [%4];"
        : "=r"(r[0]), "=r"(r[1]), "=r"(r[2]), "=r"(r[3]) : "r"(addr));
}

// ---------------- bf16 MMA GEMM, 3-stage pipeline, ONE sync/iter ------------
// CTA tile 128x128, 128 threads (4 warps 2x2), warp tile 64x64.
#define GSTG   16384u
#define NSTAGE 3
#define GEMM_SMEM (2 * NSTAGE * GSTG)     // 96 KB

template <typename OutT>
__global__ void __launch_bounds__(128, 2)
gemm_bf16(const __nv_bfloat16* __restrict__ A, const __nv_bfloat16* __restrict__ Bt,
          OutT* __restrict__ C, int M, int N, int lda, int ldb, int Kslice,
          const float* __restrict__ residual) {
    extern __shared__ char smem[];
    uint32_t smem_base;
    asm("{ .reg .u64 t; cvta.to.shared.u64 t, %1; cvt.u32.u64 %0, t; }"
        : "=r"(smem_base) : "l"(smem));

    int tid  = threadIdx.x;
    int lane = tid & 31, wid = tid >> 5;
    int bm = blockIdx.y * 128, bn = blockIdx.x * 128;
    int wm = (wid >> 1) * 64, wn = (wid & 1) * 64;
    int gid = lane >> 2, tig = lane & 3;
    int koff = blockIdx.z * Kslice;

    float acc[4][8][4];
    #pragma unroll
    for (int i = 0; i < 4; i++)
        #pragma unroll
        for (int j = 0; j < 8; j++)
            #pragma unroll
            for (int q = 0; q < 4; q++) acc[i][j][q] = 0.f;

    const __nv_bfloat16* abase = A + (size_t)bm * lda + koff;
    const __nv_bfloat16* bbase = Bt + (size_t)bn * ldb + koff;
    OutT* Cz = C + (size_t)blockIdx.z * M * N;

    int lrow = tid >> 3;
    int lch  = tid & 7;

    auto load_stage = [&](int s, int kt) {
        uint32_t adst = smem_base + (uint32_t)s * GSTG;
        uint32_t bdst = smem_base + NSTAGE * GSTG + (uint32_t)s * GSTG;
        const __nv_bfloat16* asrc = abase + (size_t)kt * 64;
        const __nv_bfloat16* bsrc = bbase + (size_t)kt * 64;
        #pragma unroll
        for (int u = 0; u < 8; u++) {
            int row = lrow + u * 16;
            uint32_t d = (uint32_t)row * 128 + ((uint32_t)(lch ^ (row & 7)) << 4);
            cp16(adst + d, asrc + (size_t)row * lda + lch * 8);
            cp16(bdst + d, bsrc + (size_t)row * ldb + lch * 8);
        }
        asm volatile("cp.async.commit_group;\n");
    };

    int nt = Kslice / 64;
    load_stage(0, 0);
    load_stage(1, 1);

    for (int t = 0; t < nt; t++) {
        int s = t % NSTAGE;
        if (t + 1 < nt) asm volatile("cp.async.wait_group 1;\n" ::: "memory");
        else            asm volatile("cp.async.wait_group 0;\n" ::: "memory");
        __syncthreads();
        if (t + 2 < nt) load_stage((t + 2) % NSTAGE, t + 2);

        uint32_t abase_s = smem_base + (uint32_t)s * GSTG;
        uint32_t bbase_s = smem_base + NSTAGE * GSTG + (uint32_t)s * GSTG;

        #pragma unroll
        for (int ks = 0; ks < 4; ks++) {
            int k8 = ks * 2;
            uint32_t af[4][4];
            #pragma unroll
            for (int i = 0; i < 4; i++) {
                int row = wm + i * 16 + (lane & 15);
                uint32_t ch = (uint32_t)((k8 + (lane >> 4)) ^ (row & 7));
                ldmx4(af[i], abase_s + (uint32_t)row * 128 + (ch << 4));
            }
            uint32_t b0[8], b1[8];
            #pragma unroll
            for (int h = 0; h < 2; h++) {
                int rowb = wn + h * 32 + lane;
                uint32_t c0 = (uint32_t)((k8    ) ^ (rowb & 7));
                uint32_t c1 = (uint32_t)((k8 + 1) ^ (rowb & 7));
                ldmx4(&b0[h * 4], bbase_s + (uint32_t)rowb * 128 + (c0 << 4));
                ldmx4(&b1[h * 4], bbase_s + (uint32_t)rowb * 128 + (c1 << 4));
            }
            #pragma unroll
            for (int i = 0; i < 4; i++)
                #pragma unroll
                for (int j = 0; j < 8; j++)
                    mma_bf16(acc[i][j], af[i][0], af[i][1], af[i][2], af[i][3],
                             b0[j], b1[j]);
        }
    }

    // ---- epilogue ----
    #pragma unroll
    for (int i = 0; i < 4; i++) {
        int r0 = bm + wm + i * 16 + gid;
        #pragma unroll
        for (int j = 0; j < 8; j++) {
            int c0 = bn + wn + j * 8 + tig * 2;
            float v0 = acc[i][j][0], v1 = acc[i][j][1];
            float v2 = acc[i][j][2], v3 = acc[i][j][3];
            if (residual) {
                const float* rr0 = residual + (size_t)r0 * N + c0;
                const float* rr1 = residual + (size_t)(r0 + 8) * N + c0;
                v0 += rr0[0]; v1 += rr0[1]; v2 += rr1[0]; v3 += rr1[1];
            }
            if constexpr (sizeof(OutT) == 2) {
                __nv_bfloat162 p0 = { __float2bfloat16(v0), __float2bfloat16(v1) };
                __nv_bfloat162 p1 = { __float2bfloat16(v2), __float2bfloat16(v3) };
                *(__nv_bfloat162*)((__nv_bfloat16*)Cz + (size_t)r0 * N + c0)       = p0;
                *(__nv_bfloat162*)((__nv_bfloat16*)Cz + (size_t)(r0 + 8) * N + c0) = p1;
            } else {
                float2 q0 = { v0, v1 }, q1 = { v2, v3 };
                *(float2*)((float*)Cz + (size_t)r0 * N + c0)       = q0;
                *(float2*)((float*)Cz + (size_t)(r0 + 8) * N + c0) = q1;
            }
        }
    }
}

// ---------------- fused prep: rmsnorm + 3 weight transposes ----------------
__device__ __forceinline__ void wtrans_body(const float* __restrict__ W,
                                            __nv_bfloat16* __restrict__ Wt,
                                            int K, int Nsrc, int bx, int by) {
    __shared__ float tile[32][33];
    int tx = threadIdx.x & 31, ty = threadIdx.x >> 5;
    #pragma unroll
    for (int r = 0; r < 32; r += 8) {
        int n = bx + tx;
        tile[ty + r][tx] = (n < Nsrc) ? W[(size_t)(by + ty + r) * Nsrc + n] : 0.f;
    }
    __syncthreads();
    #pragma unroll
    for (int r = 0; r < 32; r += 8)
        Wt[(size_t)(bx + ty + r) * K + by + tx] = __float2bfloat16(tile[tx][ty + r]);
}

__global__ void prep_kernel(const float* __restrict__ x0,
                            const float* __restrict__ norm_w,
                            const float* __restrict__ W_in,
                            const float* __restrict__ W_out,
                            const float* __restrict__ W_x) {
    int bid = blockIdx.x;
    if (bid < TOK) {
        int t = bid;
        const float* xr = x0 + (size_t)t * DMODEL;
        float s = 0.f;
        #pragma unroll
        for (int i = 0; i < DMODEL / 256; i++) {
            float v = xr[threadIdx.x + i * 256];
            s += v * v;
        }
        #pragma unroll
        for (int o = 16; o > 0; o >>= 1) s += __shfl_xor_sync(0xffffffffu, s, o);
        __shared__ float ws[8];
        if ((threadIdx.x & 31) == 0) ws[threadIdx.x >> 5] = s;
        __syncthreads();
        if (threadIdx.x < 8) {
            float v = ws[threadIdx.x];
            #pragma unroll
            for (int o = 4; o > 0; o >>= 1) v += __shfl_xor_sync(0xffu, v, o);
            if (threadIdx.x == 0) ws[0] = v;
        }
        __syncthreads();
        float rs = rsqrtf(ws[0] / (float)DMODEL + EPS);
        __nv_bfloat16* hr = g_hb + (size_t)t * DMODEL;
        #pragma unroll
        for (int i = 0; i < DMODEL / 256; i++) {
            int c = threadIdx.x + i * 256;
            hr[c] = __float2bfloat16(xr[c] * rs * norm_w[c]);
        }
    } else if (bid < TOK + 4096) {
        int t = bid - TOK;
        wtrans_body(W_in, g_wint, DMODEL, 2 * DINNER, (t & 127) * 32, (t >> 7) * 32);
    } else if (bid < TOK + 4096 + 2048) {
        int t = bid - TOK - 4096;
        wtrans_body(W_out, g_woutt, DINNER, DMODEL, (t & 31) * 32, (t >> 5) * 32);
    } else {
        int t = bid - TOK - 4096 - 2048;
        wtrans_body(W_x, g_wxt, DINNER, XDBL_N, (t & 3) * 32, (t >> 2) * 32);
    }
}
#define PREP_BLOCKS (TOK + 4096 + 2048 + 256)

// ---------------- causal depthwise conv (K=4) + SiLU, 2 d x 4 l per thread --
__global__ void conv_silu_kernel(const float* __restrict__ conv_w,
                                 const float* __restrict__ conv_b) {
    int gidx = blockIdx.x * blockDim.x + threadIdx.x;   // (b, l0/4, d2)
    int d2 = gidx & (DINNER / 2 - 1);            // bf162 index
    int q  = gidx >> 10;
    int l4 = q & (LSEQ / 4 - 1);
    int b  = q >> 8;
    int l0 = l4 * 4;
    int d  = d2 * 2;

    float2 w0 = { conv_w[d * KCONV + 0], conv_w[(d + 1) * KCONV + 0] };
    float2 w1 = { conv_w[d * KCONV + 1], conv_w[(d + 1) * KCONV + 1] };
    float2 w2 = { conv_w[d * KCONV + 2], conv_w[(d + 1) * KCONV + 2] };
    float2 w3 = { conv_w[d * KCONV + 3], conv_w[(d + 1) * KCONV + 3] };
    float2 cb = { conv_b[d], conv_b[d + 1] };

    const size_t S2 = DINNER;                    // row stride in bf162 units
    const __nv_bfloat162* base =
        (const __nv_bfloat162*)g_xresb + (size_t)(b * LSEQ) * S2 + d2;

    float2 h0 = {0.f,0.f}, h1 = {0.f,0.f}, h2 = {0.f,0.f};
    if (l0 > 0) {
        h0 = __bfloat1622float2(base[(size_t)(l0 - 3) * S2]);
        h1 = __bfloat1622float2(base[(size_t)(l0 - 2) * S2]);
        h2 = __bfloat1622float2(base[(size_t)(l0 - 1) * S2]);
    }
    float2 c0 = __bfloat1622float2(base[(size_t)(l0 + 0) * S2]);
    float2 c1 = __bfloat1622float2(base[(size_t)(l0 + 1) * S2]);
    float2 c2 = __bfloat1622float2(base[(size_t)(l0 + 2) * S2]);
    float2 c3 = __bfloat1622float2(base[(size_t)(l0 + 3) * S2]);

    __nv_bfloat162* dst = (__nv_bfloat162*)g_xcb
        + (size_t)(b * LSEQ + l0) * (DINNER / 2) + d2;
    #define CONV1(e) do { \
        float ox = fmaf(w0.x,h0.x, fmaf(w1.x,h1.x, fmaf(w2.x,h2.x, fmaf(w3.x,c0.x, cb.x)))); \
        float oy = fmaf(w0.y,h0.y, fmaf(w1.y,h1.y, fmaf(w2.y,h2.y, fmaf(w3.y,c0.y, cb.y)))); \
        dst[(size_t)(e) * (DINNER/2)] = \
            __floats2bfloat162_rn(silu_f(ox), silu_f(oy)); \
        h0 = h1; h1 = h2; h2 = c0; c0 = c1; c1 = c2; c2 = c3; \
    } while (0)
    CONV1(0); CONV1(1); CONV1(2); CONV1(3);
    #undef CONV1
}

// ---------------- fused x_proj reduce + delta GEMM ----------------
__global__ void __launch_bounds__(512)
delta_fused_kernel(const float* __restrict__ W_dt,
                   const float* __restrict__ b_dt) {
    __shared__ float sd[16][DTRANK];
    int tid = threadIdx.x;
    int t0 = blockIdx.x * 16;

    {
        int tok  = tid >> 5;
        int col4 = tid & 31;
        int off = (t0 + tok) * (XPAD / 4) + col4;
        float4 s = { 0.f, 0.f, 0.f, 0.f };
        #pragma unroll
        for (int q = 0; q < XKSPLIT; q++) {
            float4 v = *((const float4*)(g_xpf + (size_t)q * TOK * XPAD) + off);
            s.x += v.x; s.y += v.y; s.z += v.z; s.w += v.w;
        }
        if (col4 < 16) {
            *(float4*)&sd[tok][col4 * 4] = s;
        } else {
            *((float4*)g_xdbl + off) = s;
        }
    }
    __syncthreads();

    float bb[4];
    #pragma unroll
    for (int j = 0; j < 4; j++) bb[j] = b_dt[tid + 512 * j];
    float acc[16][4];
    #pragma unroll
    for (int tok = 0; tok < 16; tok++)
        #pragma unroll
        for (int j = 0; j < 4; j++) acc[tok][j] = bb[j];

    #pragma unroll 4
    for (int k = 0; k < DTRANK; k++) {
        float w[4];
        #pragma unroll
        for (int j = 0; j < 4; j++)
            w[j] = W_dt[(size_t)k * DINNER + tid + 512 * j];
        #pragma unroll
        for (int tok = 0; tok < 16; tok++) {
            float dl = sd[tok][k];
            #pragma unroll
            for (int j = 0; j < 4; j++) acc[tok][j] = fmaf(dl, w[j], acc[tok][j]);
        }
    }
    #pragma unroll
    for (int tok = 0; tok < 16; tok++)
        #pragma unroll
        for (int j = 0; j < 4; j++) {
            float x = acc[tok][j];
            float sp = (x > 20.f) ? x : log1pf(__expf(x));
            g_deltab[(size_t)(t0 + tok) * DINNER + tid + 512 * j] =
                __float2bfloat16(sp);
        }
}

// ---------------- scan pass A ----------------
__global__ void scanA_kernel(const float* __restrict__ A) {
    int g = blockIdx.x * blockDim.x + threadIdx.x;
    int tid = threadIdx.x;
    int d  = g & (DINNER - 1);
    int bc = g >> 11;
    int c  = bc & (NCHUNK - 1);
    int b  = bc >> 5;
    int t0 = b * LSEQ + c * CLEN;

    __shared__ float sB[CLEN][DSTATE];
    {
        int l = tid >> 3, n2 = tid & 7;
        float2 v = *(const float2*)(g_xdbl + (size_t)(t0 + l) * XPAD + DTRANK + n2 * 2);
        *(float2*)&sB[l][n2 * 2] = v;
    }
    __syncthreads();

    float a[DSTATE], s[DSTATE], P[DSTATE];
    #pragma unroll
    for (int q = 0; q < 4; q++) {
        float4 v = *(const float4*)(A + d * DSTATE + q * 4);
        a[q*4+0]=v.x*LOG2E; a[q*4+1]=v.y*LOG2E; a[q*4+2]=v.z*LOG2E; a[q*4+3]=v.w*LOG2E;
    }
    #pragma unroll
    for (int n = 0; n < DSTATE; n++) { s[n] = 0.f; P[n] = 1.f; }

    for (int l = 0; l < CLEN; l++) {
        int t = t0 + l;
        float delta = __bfloat162float(g_deltab[(size_t)t * DINNER + d]);
        float xv    = __bfloat162float(g_xcb   [(size_t)t * DINNER + d]);
        float du    = delta * xv;
        #pragma unroll
        for (int n = 0; n < DSTATE; n++) {
            float dA = ex2f(delta * a[n]);
            s[n] = fmaf(dA, s[n], du * sB[l][n]);
            P[n] *= dA;
        }
    }
    float* Sp = g_S + (size_t)bc * DN + d * DSTATE;
    float* Pp = g_P + (size_t)bc * DN + d * DSTATE;
    #pragma unroll
    for (int q = 0; q < 4; q++) {
        float4 vs = { s[q*4+0], s[q*4+1], s[q*4+2], s[q*4+3] };
        float4 vp = { P[q*4+0], P[q*4+1], P[q*4+2], P[q*4+3] };
        *(float4*)(Sp + q * 4) = vs;
        *(float4*)(Pp + q * 4) = vp;
    }
}

// ---------------- scan pass B ----------------
__global__ void scanB_kernel() {
    int g = blockIdx.x * blockDim.x + threadIdx.x;
    int per_b = DN / 4;
    int b   = g / per_b;
    int i4  = g - b * per_b;
    const float4* S4  = (const float4*)g_S;
    const float4* P4  = (const float4*)g_P;
    float4*       SI4 = (float4*)g_SI;
    size_t base = (size_t)b * NCHUNK * per_b + i4;
    float4 s = { 0.f, 0.f, 0.f, 0.f };
    #pragma unroll 4
    for (int c = 0; c < NCHUNK; c++) {
        size_t o = base + (size_t)c * per_b;
        SI4[o] = s;
        float4 sv = S4[o], pv = P4[o];
        s.x = fmaf(pv.x, s.x, sv.x);
        s.y = fmaf(pv.y, s.y, sv.y);
        s.z = fmaf(pv.z, s.z, sv.z);
        s.w = fmaf(pv.w, s.w, sv.w);
    }
}

// ---------------- scan pass C ----------------
__global__ void scanC_kernel(const float* __restrict__ A,
                             const float* __restrict__ Dp) {
    int g = blockIdx.x * blockDim.x + threadIdx.x;
    int tid = threadIdx.x;
    int d  = g & (DINNER - 1);
    int bc = g >> 11;
    int c  = bc & (NCHUNK - 1);
    int b  = bc >> 5;
    int t0 = b * LSEQ + c * CLEN;

    __shared__ float sB[CLEN][DSTATE];
    __shared__ float sC[CLEN][DSTATE];
    {
        int l = tid >> 3, n2 = tid & 7;
        const float* row = g_xdbl + (size_t)(t0 + l) * XPAD + DTRANK;
        *(float2*)&sB[l][n2 * 2] = *(const float2*)(row + n2 * 2);
        *(float2*)&sC[l][n2 * 2] = *(const float2*)(row + DSTATE + n2 * 2);
    }
    __syncthreads();

    float a[DSTATE], s[DSTATE];
    #pragma unroll
    for (int q = 0; q < 4; q++) {
        float4 v = *(const float4*)(A + d * DSTATE + q * 4);
        a[q*4+0]=v.x*LOG2E; a[q*4+1]=v.y*LOG2E; a[q*4+2]=v.z*LOG2E; a[q*4+3]=v.w*LOG2E;
        float4 vi = *(const float4*)(g_SI + (size_t)bc * DN + d * DSTATE + q * 4);
        s[q*4+0]=vi.x; s[q*4+1]=vi.y; s[q*4+2]=vi.z; s[q*4+3]=vi.w;
    }
    float Dd = Dp[d];

    for (int l = 0; l < CLEN; l++) {
        int t = t0 + l;
        float delta = __bfloat162float(g_deltab[(size_t)t * DINNER + d]);
        float xv    = __bfloat162float(g_xcb   [(size_t)t * DINNER + d]);
        float du    = delta * xv;
        float y = 0.f;
        #pragma unroll
        for (int n = 0; n < DSTATE; n++) {
            float dA = ex2f(delta * a[n]);
            s[n] = fmaf(dA, s[n], du * sB[l][n]);
            y = fmaf(s[n], sC[l][n], y);
        }
        float res = __bfloat162float(
            g_xresb[(size_t)t * (2 * DINNER) + DINNER + d]);
        g_yb[(size_t)t * DINNER + d] =
            __float2bfloat16((y + xv * Dd) * silu_f(res));
    }
}

// ---------------- launch ----------------
extern "C" void kernel_launch(void* const* d_in, const int* in_sizes, int n_in,
                              void* d_out, int out_size) {
    const float* x0     = (const float*)d_in[0];
    const float* norm_w = (const float*)d_in[1];
    const float* W_in   = (const float*)d_in[2];
    const float* conv_w = (const float*)d_in[3];
    const float* conv_b = (const float*)d_in[4];
    const float* W_x    = (const float*)d_in[5];
    const float* W_dt   = (const float*)d_in[6];
    const float* b_dt   = (const float*)d_in[7];
    const float* Amat   = (const float*)d_in[8];
    const float* Dvec   = (const float*)d_in[9];
    const float* W_out  = (const float*)d_in[10];
    float* out = (float*)d_out;

    __nv_bfloat16 *p_hb, *p_yb, *p_wint, *p_woutt, *p_wxt, *p_xresb, *p_xcb;
    float *p_xpf;
    cudaGetSymbolAddress((void**)&p_hb,    g_hb);
    cudaGetSymbolAddress((void**)&p_yb,    g_yb);
    cudaGetSymbolAddress((void**)&p_wint,  g_wint);
    cudaGetSymbolAddress((void**)&p_woutt, g_woutt);
    cudaGetSymbolAddress((void**)&p_wxt,   g_wxt);
    cudaGetSymbolAddress((void**)&p_xresb, g_xresb);
    cudaGetSymbolAddress((void**)&p_xcb,   g_xcb);
    cudaGetSymbolAddress((void**)&p_xpf,   g_xpf);

    cudaFuncSetAttribute(gemm_bf16<__nv_bfloat16>,
                         cudaFuncAttributeMaxDynamicSharedMemorySize, GEMM_SMEM);
    cudaFuncSetAttribute(gemm_bf16<float>,
                         cudaFuncAttributeMaxDynamicSharedMemorySize, GEMM_SMEM);

    // 1) fused prep: rmsnorm + all weight transposes
    prep_kernel<<<PREP_BLOCKS, 256>>>(x0, norm_w, W_in, W_out, W_x);

    // 2) in_proj (bf16 mma, bf16 out): [2048,1024] @ [1024,4096]
    gemm_bf16<__nv_bfloat16><<<dim3((2 * DINNER) / 128, TOK / 128), 128, GEMM_SMEM>>>(
        p_hb, p_wint, p_xresb, TOK, 2 * DINNER, DMODEL, DMODEL, DMODEL, nullptr);

    // 3) conv + silu (2 d per thread, vectorized)
    conv_silu_kernel<<<(TOK / 4 * DINNER / 2) / 256, 256>>>(conv_w, conv_b);

    // 4) x_proj: split-K bf16 mma -> partials
    gemm_bf16<float><<<dim3(1, TOK / 128, XKSPLIT), 128, GEMM_SMEM>>>(
        p_xcb, p_wxt, p_xpf, TOK, XPAD, DINNER, DINNER, DINNER / XKSPLIT, nullptr);

    // 5) fused reduce + delta
    delta_fused_kernel<<<TOK / 16, 512>>>(W_dt, b_dt);

    // 6) chunked selective scan
    scanA_kernel<<<(BATCH * NCHUNK * DINNER) / 256, 256>>>(Amat);
    scanB_kernel<<<(BATCH * DN / 4) / 256, 256>>>();
    scanC_kernel<<<(BATCH * NCHUNK * DINNER) / 256, 256>>>(Amat, Dvec);

    // 7) out_proj (bf16 mma, fp32 out) + residual: [2048,2048] @ [2048,1024]
    gemm_bf16<float><<<dim3(DMODEL / 128, TOK / 128), 128, GEMM_SMEM>>>(
        p_yb, p_woutt, out, TOK, DMODEL, DINNER, DINNER, DINNER, x0);
}

// round 14
// speedup vs baseline: 1.0085x; 1.0085x over previous
#include <cuda_runtime.h>
#include <cuda_bf16.h>
#include <math.h>
#include <stdint.h>

// ---------------- problem constants ----------------
#define BATCH   2
#define LSEQ    1024
#define DMODEL  1024
#define DINNER  2048
#define DSTATE  16
#define DTRANK  64
#define KCONV   4
#define TOK     (BATCH*LSEQ)        // 2048 tokens
#define XDBL_N  96
#define XPAD    128                 // padded xdbl stride
#define EPS     1e-5f
#define LOG2E   1.44269504088896f

#define NCHUNK  32
#define CLEN    (LSEQ/NCHUNK)       // 32
#define DN      (DINNER*DSTATE)     // 32768
#define XKSPLIT 8                   // x_proj K splits (MMA)

// ---------------- scratch ----------------
__device__ __align__(16) __nv_bfloat16 g_hb    [TOK * DMODEL];       // rmsnorm out
__device__ __align__(16) __nv_bfloat16 g_yb    [TOK * DINNER];       // scan out
__device__ __align__(16) __nv_bfloat16 g_wint  [2*DINNER * DMODEL];  // W_in^T
__device__ __align__(16) __nv_bfloat16 g_woutt [DMODEL * DINNER];    // W_out^T
__device__ __align__(16) __nv_bfloat16 g_wxt   [XPAD * DINNER];      // W_x^T padded
__device__ __align__(16) __nv_bfloat16 g_xresb [TOK * 2 * DINNER];   // in_proj out
__device__ __align__(16) __nv_bfloat16 g_xcb   [TOK * DINNER];       // conv+silu out
__device__ __align__(16) __nv_bfloat16 g_deltab[TOK * DINNER];       // softplus(dt)
__device__ __align__(16) float g_xdbl [TOK * XPAD];                  // B/C cols used
__device__ __align__(16) float g_xpf  [XKSPLIT * TOK * XPAD];        // x_proj partials
__device__ __align__(16) float g_S    [BATCH * NCHUNK * DN];
__device__ __align__(16) float g_P    [BATCH * NCHUNK * DN];
__device__ __align__(16) float g_SI   [BATCH * NCHUNK * DN];

// ---------------- helpers ----------------
__device__ __forceinline__ float silu_f(float x) {
    return x / (1.f + __expf(-x));
}
__device__ __forceinline__ float ex2f(float x) {
    float r;
    asm("ex2.approx.f32 %0, %1;" : "=f"(r) : "f"(x));
    return r;
}
__device__ __forceinline__ void cp16(uint32_t smem, const void* g) {
    asm volatile("cp.async.cg.shared.global [%0], [%1], 16;\n" :: "r"(smem), "l"(g));
}
__device__ __forceinline__ void mma_bf16(float c[4],
    uint32_t a0, uint32_t a1, uint32_t a2, uint32_t a3,
    uint32_t b0, uint32_t b1) {
    asm volatile(
        "mma.sync.aligned.m16n8k16.row.col.f32.bf16.bf16.f32 "
        "{%0,%1,%2,%3}, {%4,%5,%6,%7}, {%8,%9}, {%0,%1,%2,%3};"
        : "+f"(c[0]), "+f"(c[1]), "+f"(c[2]), "+f"(c[3])
        : "r"(a0), "r"(a1), "r"(a2), "r"(a3), "r"(b0), "r"(b1));
}
__device__ __forceinline__ void ldmx4(uint32_t r[4], uint32_t addr) {
    asm volatile(
        "ldmatrix.sync.aligned.m8n8.x4.shared.b16 {%0,%1,%2,%3}, [%4];"
        : "=r"(r[0]), "=r"(r[1]), "=r"(r[2]), "=r"(r[3]) : "r"(addr));
}

// ---------------- bf16 MMA GEMM, 3-stage pipeline, ONE sync/iter ------------
// CTA tile 128x128, 128 threads (4 warps 2x2), warp tile 64x64.
#define GSTG   16384u
#define NSTAGE 3
#define GEMM_SMEM (2 * NSTAGE * GSTG)     // 96 KB

template <typename OutT>
__global__ void __launch_bounds__(128, 2)
gemm_bf16(const __nv_bfloat16* __restrict__ A, const __nv_bfloat16* __restrict__ Bt,
          OutT* __restrict__ C, int M, int N, int lda, int ldb, int Kslice,
          const float* __restrict__ residual) {
    extern __shared__ char smem[];
    uint32_t smem_base;
    asm("{ .reg .u64 t; cvta.to.shared.u64 t, %1; cvt.u32.u64 %0, t; }"
        : "=r"(smem_base) : "l"(smem));

    int tid  = threadIdx.x;
    int lane = tid & 31, wid = tid >> 5;
    int bm = blockIdx.y * 128, bn = blockIdx.x * 128;
    int wm = (wid >> 1) * 64, wn = (wid & 1) * 64;
    int gid = lane >> 2, tig = lane & 3;
    int koff = blockIdx.z * Kslice;

    float acc[4][8][4];
    #pragma unroll
    for (int i = 0; i < 4; i++)
        #pragma unroll
        for (int j = 0; j < 8; j++)
            #pragma unroll
            for (int q = 0; q < 4; q++) acc[i][j][q] = 0.f;

    const __nv_bfloat16* abase = A + (size_t)bm * lda + koff;
    const __nv_bfloat16* bbase = Bt + (size_t)bn * ldb + koff;
    OutT* Cz = C + (size_t)blockIdx.z * M * N;

    int lrow = tid >> 3;
    int lch  = tid & 7;

    auto load_stage = [&](int s, int kt) {
        uint32_t adst = smem_base + (uint32_t)s * GSTG;
        uint32_t bdst = smem_base + NSTAGE * GSTG + (uint32_t)s * GSTG;
        const __nv_bfloat16* asrc = abase + (size_t)kt * 64;
        const __nv_bfloat16* bsrc = bbase + (size_t)kt * 64;
        #pragma unroll
        for (int u = 0; u < 8; u++) {
            int row = lrow + u * 16;
            uint32_t d = (uint32_t)row * 128 + ((uint32_t)(lch ^ (row & 7)) << 4);
            cp16(adst + d, asrc + (size_t)row * lda + lch * 8);
            cp16(bdst + d, bsrc + (size_t)row * ldb + lch * 8);
        }
        asm volatile("cp.async.commit_group;\n");
    };

    int nt = Kslice / 64;
    load_stage(0, 0);
    load_stage(1, 1);

    for (int t = 0; t < nt; t++) {
        int s = t % NSTAGE;
        if (t + 1 < nt) asm volatile("cp.async.wait_group 1;\n" ::: "memory");
        else            asm volatile("cp.async.wait_group 0;\n" ::: "memory");
        __syncthreads();
        if (t + 2 < nt) load_stage((t + 2) % NSTAGE, t + 2);

        uint32_t abase_s = smem_base + (uint32_t)s * GSTG;
        uint32_t bbase_s = smem_base + NSTAGE * GSTG + (uint32_t)s * GSTG;

        #pragma unroll
        for (int ks = 0; ks < 4; ks++) {
            int k8 = ks * 2;
            uint32_t af[4][4];
            #pragma unroll
            for (int i = 0; i < 4; i++) {
                int row = wm + i * 16 + (lane & 15);
                uint32_t ch = (uint32_t)((k8 + (lane >> 4)) ^ (row & 7));
                ldmx4(af[i], abase_s + (uint32_t)row * 128 + (ch << 4));
            }
            uint32_t b0[8], b1[8];
            #pragma unroll
            for (int h = 0; h < 2; h++) {
                int rowb = wn + h * 32 + lane;
                uint32_t c0 = (uint32_t)((k8    ) ^ (rowb & 7));
                uint32_t c1 = (uint32_t)((k8 + 1) ^ (rowb & 7));
                ldmx4(&b0[h * 4], bbase_s + (uint32_t)rowb * 128 + (c0 << 4));
                ldmx4(&b1[h * 4], bbase_s + (uint32_t)rowb * 128 + (c1 << 4));
            }
            #pragma unroll
            for (int i = 0; i < 4; i++)
                #pragma unroll
                for (int j = 0; j < 8; j++)
                    mma_bf16(acc[i][j], af[i][0], af[i][1], af[i][2], af[i][3],
                             b0[j], b1[j]);
        }
    }

    // ---- epilogue ----
    #pragma unroll
    for (int i = 0; i < 4; i++) {
        int r0 = bm + wm + i * 16 + gid;
        #pragma unroll
        for (int j = 0; j < 8; j++) {
            int c0 = bn + wn + j * 8 + tig * 2;
            float v0 = acc[i][j][0], v1 = acc[i][j][1];
            float v2 = acc[i][j][2], v3 = acc[i][j][3];
            if (residual) {
                const float* rr0 = residual + (size_t)r0 * N + c0;
                const float* rr1 = residual + (size_t)(r0 + 8) * N + c0;
                v0 += rr0[0]; v1 += rr0[1]; v2 += rr1[0]; v3 += rr1[1];
            }
            if constexpr (sizeof(OutT) == 2) {
                __nv_bfloat162 p0 = { __float2bfloat16(v0), __float2bfloat16(v1) };
                __nv_bfloat162 p1 = { __float2bfloat16(v2), __float2bfloat16(v3) };
                *(__nv_bfloat162*)((__nv_bfloat16*)Cz + (size_t)r0 * N + c0)       = p0;
                *(__nv_bfloat162*)((__nv_bfloat16*)Cz + (size_t)(r0 + 8) * N + c0) = p1;
            } else {
                float2 q0 = { v0, v1 }, q1 = { v2, v3 };
                *(float2*)((float*)Cz + (size_t)r0 * N + c0)       = q0;
                *(float2*)((float*)Cz + (size_t)(r0 + 8) * N + c0) = q1;
            }
        }
    }
}

// ---------------- fused prep: rmsnorm + 3 weight transposes ----------------
__device__ __forceinline__ void wtrans_body(const float* __restrict__ W,
                                            __nv_bfloat16* __restrict__ Wt,
                                            int K, int Nsrc, int bx, int by) {
    __shared__ float tile[32][33];
    int tx = threadIdx.x & 31, ty = threadIdx.x >> 5;
    #pragma unroll
    for (int r = 0; r < 32; r += 8) {
        int n = bx + tx;
        tile[ty + r][tx] = (n < Nsrc) ? W[(size_t)(by + ty + r) * Nsrc + n] : 0.f;
    }
    __syncthreads();
    #pragma unroll
    for (int r = 0; r < 32; r += 8)
        Wt[(size_t)(bx + ty + r) * K + by + tx] = __float2bfloat16(tile[tx][ty + r]);
}

__global__ void prep_kernel(const float* __restrict__ x0,
                            const float* __restrict__ norm_w,
                            const float* __restrict__ W_in,
                            const float* __restrict__ W_out,
                            const float* __restrict__ W_x) {
    int bid = blockIdx.x;
    if (bid < TOK) {
        int t = bid;
        const float* xr = x0 + (size_t)t * DMODEL;
        float s = 0.f;
        #pragma unroll
        for (int i = 0; i < DMODEL / 256; i++) {
            float v = xr[threadIdx.x + i * 256];
            s += v * v;
        }
        #pragma unroll
        for (int o = 16; o > 0; o >>= 1) s += __shfl_xor_sync(0xffffffffu, s, o);
        __shared__ float ws[8];
        if ((threadIdx.x & 31) == 0) ws[threadIdx.x >> 5] = s;
        __syncthreads();
        if (threadIdx.x < 8) {
            float v = ws[threadIdx.x];
            #pragma unroll
            for (int o = 4; o > 0; o >>= 1) v += __shfl_xor_sync(0xffu, v, o);
            if (threadIdx.x == 0) ws[0] = v;
        }
        __syncthreads();
        float rs = rsqrtf(ws[0] / (float)DMODEL + EPS);
        __nv_bfloat16* hr = g_hb + (size_t)t * DMODEL;
        #pragma unroll
        for (int i = 0; i < DMODEL / 256; i++) {
            int c = threadIdx.x + i * 256;
            hr[c] = __float2bfloat16(xr[c] * rs * norm_w[c]);
        }
    } else if (bid < TOK + 4096) {
        int t = bid - TOK;
        wtrans_body(W_in, g_wint, DMODEL, 2 * DINNER, (t & 127) * 32, (t >> 7) * 32);
    } else if (bid < TOK + 4096 + 2048) {
        int t = bid - TOK - 4096;
        wtrans_body(W_out, g_woutt, DINNER, DMODEL, (t & 31) * 32, (t >> 5) * 32);
    } else {
        int t = bid - TOK - 4096 - 2048;
        wtrans_body(W_x, g_wxt, DINNER, XDBL_N, (t & 3) * 32, (t >> 2) * 32);
    }
}
#define PREP_BLOCKS (TOK + 4096 + 2048 + 256)

// ---------------- causal depthwise conv (K=4) + SiLU, 4 outputs/thread ------
// (scalar per-d form: independent FMA trees, max ILP — round-11 version)
__global__ void conv_silu_kernel(const float* __restrict__ conv_w,
                                 const float* __restrict__ conv_b) {
    int gidx = blockIdx.x * blockDim.x + threadIdx.x;
    int d  = gidx & (DINNER - 1);
    int q  = gidx >> 11;
    int l4 = q & (LSEQ / 4 - 1);
    int b  = q >> 8;
    int l0 = l4 * 4;

    float w0 = conv_w[d * KCONV + 0];
    float w1 = conv_w[d * KCONV + 1];
    float w2 = conv_w[d * KCONV + 2];
    float w3 = conv_w[d * KCONV + 3];
    float cb = conv_b[d];

    const size_t S = 2 * DINNER;
    const __nv_bfloat16* base = g_xresb + (size_t)(b * LSEQ) * S + d;

    float h0 = 0.f, h1 = 0.f, h2 = 0.f;
    if (l0 > 0) {
        h0 = __bfloat162float(base[(size_t)(l0 - 3) * S]);
        h1 = __bfloat162float(base[(size_t)(l0 - 2) * S]);
        h2 = __bfloat162float(base[(size_t)(l0 - 1) * S]);
    }
    float c0 = __bfloat162float(base[(size_t)(l0 + 0) * S]);
    float c1 = __bfloat162float(base[(size_t)(l0 + 1) * S]);
    float c2 = __bfloat162float(base[(size_t)(l0 + 2) * S]);
    float c3 = __bfloat162float(base[(size_t)(l0 + 3) * S]);

    float o0 = fmaf(w0,h0, fmaf(w1,h1, fmaf(w2,h2, fmaf(w3,c0, cb))));
    float o1 = fmaf(w0,h1, fmaf(w1,h2, fmaf(w2,c0, fmaf(w3,c1, cb))));
    float o2 = fmaf(w0,h2, fmaf(w1,c0, fmaf(w2,c1, fmaf(w3,c2, cb))));
    float o3 = fmaf(w0,c0, fmaf(w1,c1, fmaf(w2,c2, fmaf(w3,c3, cb))));

    size_t t0 = (size_t)(b * LSEQ + l0) * DINNER + d;
    g_xcb[t0]              = __float2bfloat16(silu_f(o0));
    g_xcb[t0 + DINNER]     = __float2bfloat16(silu_f(o1));
    g_xcb[t0 + 2 * DINNER] = __float2bfloat16(silu_f(o2));
    g_xcb[t0 + 3 * DINNER] = __float2bfloat16(silu_f(o3));
}

// ---------------- fused x_proj reduce + delta GEMM ----------------
__global__ void __launch_bounds__(512)
delta_fused_kernel(const float* __restrict__ W_dt,
                   const float* __restrict__ b_dt) {
    __shared__ float sd[16][DTRANK];
    int tid = threadIdx.x;
    int t0 = blockIdx.x * 16;

    {
        int tok  = tid >> 5;
        int col4 = tid & 31;
        int off = (t0 + tok) * (XPAD / 4) + col4;
        float4 s = { 0.f, 0.f, 0.f, 0.f };
        #pragma unroll
        for (int q = 0; q < XKSPLIT; q++) {
            float4 v = *((const float4*)(g_xpf + (size_t)q * TOK * XPAD) + off);
            s.x += v.x; s.y += v.y; s.z += v.z; s.w += v.w;
        }
        if (col4 < 16) {
            *(float4*)&sd[tok][col4 * 4] = s;
        } else {
            *((float4*)g_xdbl + off) = s;
        }
    }
    __syncthreads();

    float bb[4];
    #pragma unroll
    for (int j = 0; j < 4; j++) bb[j] = b_dt[tid + 512 * j];
    float acc[16][4];
    #pragma unroll
    for (int tok = 0; tok < 16; tok++)
        #pragma unroll
        for (int j = 0; j < 4; j++) acc[tok][j] = bb[j];

    #pragma unroll 4
    for (int k = 0; k < DTRANK; k++) {
        float w[4];
        #pragma unroll
        for (int j = 0; j < 4; j++)
            w[j] = W_dt[(size_t)k * DINNER + tid + 512 * j];
        #pragma unroll
        for (int tok = 0; tok < 16; tok++) {
            float dl = sd[tok][k];
            #pragma unroll
            for (int j = 0; j < 4; j++) acc[tok][j] = fmaf(dl, w[j], acc[tok][j]);
        }
    }
    #pragma unroll
    for (int tok = 0; tok < 16; tok++)
        #pragma unroll
        for (int j = 0; j < 4; j++) {
            float x = acc[tok][j];
            float sp = (x > 20.f) ? x : log1pf(__expf(x));
            g_deltab[(size_t)(t0 + tok) * DINNER + tid + 512 * j] =
                __float2bfloat16(sp);
        }
}

// ---------------- scan pass A ----------------
__global__ void scanA_kernel(const float* __restrict__ A) {
    int g = blockIdx.x * blockDim.x + threadIdx.x;
    int tid = threadIdx.x;
    int d  = g & (DINNER - 1);
    int bc = g >> 11;
    int c  = bc & (NCHUNK - 1);
    int b  = bc >> 5;
    int t0 = b * LSEQ + c * CLEN;

    __shared__ float sB[CLEN][DSTATE];
    {
        int l = tid >> 3, n2 = tid & 7;
        float2 v = *(const float2*)(g_xdbl + (size_t)(t0 + l) * XPAD + DTRANK + n2 * 2);
        *(float2*)&sB[l][n2 * 2] = v;
    }
    __syncthreads();

    float a[DSTATE], s[DSTATE], P[DSTATE];
    #pragma unroll
    for (int q = 0; q < 4; q++) {
        float4 v = *(const float4*)(A + d * DSTATE + q * 4);
        a[q*4+0]=v.x*LOG2E; a[q*4+1]=v.y*LOG2E; a[q*4+2]=v.z*LOG2E; a[q*4+3]=v.w*LOG2E;
    }
    #pragma unroll
    for (int n = 0; n < DSTATE; n++) { s[n] = 0.f; P[n] = 1.f; }

    for (int l = 0; l < CLEN; l++) {
        int t = t0 + l;
        float delta = __bfloat162float(g_deltab[(size_t)t * DINNER + d]);
        float xv    = __bfloat162float(g_xcb   [(size_t)t * DINNER + d]);
        float du    = delta * xv;
        #pragma unroll
        for (int n = 0; n < DSTATE; n++) {
            float dA = ex2f(delta * a[n]);
            s[n] = fmaf(dA, s[n], du * sB[l][n]);
            P[n] *= dA;
        }
    }
    float* Sp = g_S + (size_t)bc * DN + d * DSTATE;
    float* Pp = g_P + (size_t)bc * DN + d * DSTATE;
    #pragma unroll
    for (int q = 0; q < 4; q++) {
        float4 vs = { s[q*4+0], s[q*4+1], s[q*4+2], s[q*4+3] };
        float4 vp = { P[q*4+0], P[q*4+1], P[q*4+2], P[q*4+3] };
        *(float4*)(Sp + q * 4) = vs;
        *(float4*)(Pp + q * 4) = vp;
    }
}

// ---------------- scan pass B ----------------
__global__ void scanB_kernel() {
    int g = blockIdx.x * blockDim.x + threadIdx.x;
    int per_b = DN / 4;
    int b   = g / per_b;
    int i4  = g - b * per_b;
    const float4* S4  = (const float4*)g_S;
    const float4* P4  = (const float4*)g_P;
    float4*       SI4 = (float4*)g_SI;
    size_t base = (size_t)b * NCHUNK * per_b + i4;
    float4 s = { 0.f, 0.f, 0.f, 0.f };
    #pragma unroll 4
    for (int c = 0; c < NCHUNK; c++) {
        size_t o = base + (size_t)c * per_b;
        SI4[o] = s;
        float4 sv = S4[o], pv = P4[o];
        s.x = fmaf(pv.x, s.x, sv.x);
        s.y = fmaf(pv.y, s.y, sv.y);
        s.z = fmaf(pv.z, s.z, sv.z);
        s.w = fmaf(pv.w, s.w, sv.w);
    }
}

// ---------------- scan pass C ----------------
__global__ void scanC_kernel(const float* __restrict__ A,
                             const float* __restrict__ Dp) {
    int g = blockIdx.x * blockDim.x + threadIdx.x;
    int tid = threadIdx.x;
    int d  = g & (DINNER - 1);
    int bc = g >> 11;
    int c  = bc & (NCHUNK - 1);
    int b  = bc >> 5;
    int t0 = b * LSEQ + c * CLEN;

    __shared__ float sB[CLEN][DSTATE];
    __shared__ float sC[CLEN][DSTATE];
    {
        int l = tid >> 3, n2 = tid & 7;
        const float* row = g_xdbl + (size_t)(t0 + l) * XPAD + DTRANK;
        *(float2*)&sB[l][n2 * 2] = *(const float2*)(row + n2 * 2);
        *(float2*)&sC[l][n2 * 2] = *(const float2*)(row + DSTATE + n2 * 2);
    }
    __syncthreads();

    float a[DSTATE], s[DSTATE];
    #pragma unroll
    for (int q = 0; q < 4; q++) {
        float4 v = *(const float4*)(A + d * DSTATE + q * 4);
        a[q*4+0]=v.x*LOG2E; a[q*4+1]=v.y*LOG2E; a[q*4+2]=v.z*LOG2E; a[q*4+3]=v.w*LOG2E;
        float4 vi = *(const float4*)(g_SI + (size_t)bc * DN + d * DSTATE + q * 4);
        s[q*4+0]=vi.x; s[q*4+1]=vi.y; s[q*4+2]=vi.z; s[q*4+3]=vi.w;
    }
    float Dd = Dp[d];

    for (int l = 0; l < CLEN; l++) {
        int t = t0 + l;
        float delta = __bfloat162float(g_deltab[(size_t)t * DINNER + d]);
        float xv    = __bfloat162float(g_xcb   [(size_t)t * DINNER + d]);
        float du    = delta * xv;
        float y = 0.f;
        #pragma unroll
        for (int n = 0; n < DSTATE; n++) {
            float dA = ex2f(delta * a[n]);
            s[n] = fmaf(dA, s[n], du * sB[l][n]);
            y = fmaf(s[n], sC[l][n], y);
        }
        float res = __bfloat162float(
            g_xresb[(size_t)t * (2 * DINNER) + DINNER + d]);
        g_yb[(size_t)t * DINNER + d] =
            __float2bfloat16((y + xv * Dd) * silu_f(res));
    }
}

// ---------------- launch ----------------
extern "C" void kernel_launch(void* const* d_in, const int* in_sizes, int n_in,
                              void* d_out, int out_size) {
    const float* x0     = (const float*)d_in[0];
    const float* norm_w = (const float*)d_in[1];
    const float* W_in   = (const float*)d_in[2];
    const float* conv_w = (const float*)d_in[3];
    const float* conv_b = (const float*)d_in[4];
    const float* W_x    = (const float*)d_in[5];
    const float* W_dt   = (const float*)d_in[6];
    const float* b_dt   = (const float*)d_in[7];
    const float* Amat   = (const float*)d_in[8];
    const float* Dvec   = (const float*)d_in[9];
    const float* W_out  = (const float*)d_in[10];
    float* out = (float*)d_out;

    __nv_bfloat16 *p_hb, *p_yb, *p_wint, *p_woutt, *p_wxt, *p_xresb, *p_xcb;
    float *p_xpf;
    cudaGetSymbolAddress((void**)&p_hb,    g_hb);
    cudaGetSymbolAddress((void**)&p_yb,    g_yb);
    cudaGetSymbolAddress((void**)&p_wint,  g_wint);
    cudaGetSymbolAddress((void**)&p_woutt, g_woutt);
    cudaGetSymbolAddress((void**)&p_wxt,   g_wxt);
    cudaGetSymbolAddress((void**)&p_xresb, g_xresb);
    cudaGetSymbolAddress((void**)&p_xcb,   g_xcb);
    cudaGetSymbolAddress((void**)&p_xpf,   g_xpf);

    cudaFuncSetAttribute(gemm_bf16<__nv_bfloat16>,
                         cudaFuncAttributeMaxDynamicSharedMemorySize, GEMM_SMEM);
    cudaFuncSetAttribute(gemm_bf16<float>,
                         cudaFuncAttributeMaxDynamicSharedMemorySize, GEMM_SMEM);

    // 1) fused prep: rmsnorm + all weight transposes
    prep_kernel<<<PREP_BLOCKS, 256>>>(x0, norm_w, W_in, W_out, W_x);

    // 2) in_proj (bf16 mma, bf16 out): [2048,1024] @ [1024,4096]
    gemm_bf16<__nv_bfloat16><<<dim3((2 * DINNER) / 128, TOK / 128), 128, GEMM_SMEM>>>(
        p_hb, p_wint, p_xresb, TOK, 2 * DINNER, DMODEL, DMODEL, DMODEL, nullptr);

    // 3) conv + silu (scalar, 4 outputs/thread)
    conv_silu_kernel<<<(TOK / 4 * DINNER) / 256, 256>>>(conv_w, conv_b);

    // 4) x_proj: split-K bf16 mma -> partials
    gemm_bf16<float><<<dim3(1, TOK / 128, XKSPLIT), 128, GEMM_SMEM>>>(
        p_xcb, p_wxt, p_xpf, TOK, XPAD, DINNER, DINNER, DINNER / XKSPLIT, nullptr);

    // 5) fused reduce + delta
    delta_fused_kernel<<<TOK / 16, 512>>>(W_dt, b_dt);

    // 6) chunked selective scan
    scanA_kernel<<<(BATCH * NCHUNK * DINNER) / 256, 256>>>(Amat);
    scanB_kernel<<<(BATCH * DN / 4) / 256, 256>>>();
    scanC_kernel<<<(BATCH * NCHUNK * DINNER) / 256, 256>>>(Amat, Dvec);

    // 7) out_proj (bf16 mma, fp32 out) + residual: [2048,2048] @ [2048,1024]
    gemm_bf16<float><<<dim3(DMODEL / 128, TOK / 128), 128, GEMM_SMEM>>>(
        p_yb, p_woutt, out, TOK, DMODEL, DINNER, DINNER, DINNER, x0);
}

// round 15
// speedup vs baseline: 1.0243x; 1.0156x over previous
#include <cuda_runtime.h>
#include <cuda_bf16.h>
#include <math.h>
#include <stdint.h>

// ---------------- problem constants ----------------
#define BATCH   2
#define LSEQ    1024
#define DMODEL  1024
#define DINNER  2048
#define DSTATE  16
#define DTRANK  64
#define KCONV   4
#define TOK     (BATCH*LSEQ)        // 2048 tokens
#define XDBL_N  96
#define XPAD    128                 // padded xdbl stride
#define EPS     1e-5f
#define LOG2E   1.44269504088896f

#define NCHUNK  32
#define CLEN    (LSEQ/NCHUNK)       // 32
#define DN      (DINNER*DSTATE)     // 32768
#define XKSPLIT 16                  // x_proj K splits (MMA)

// ---------------- scratch ----------------
__device__ __align__(16) __nv_bfloat16 g_hb    [TOK * DMODEL];       // rmsnorm out
__device__ __align__(16) __nv_bfloat16 g_yb    [TOK * DINNER];       // scan out
__device__ __align__(16) __nv_bfloat16 g_wint  [2*DINNER * DMODEL];  // W_in^T
__device__ __align__(16) __nv_bfloat16 g_woutt [DMODEL * DINNER];    // W_out^T
__device__ __align__(16) __nv_bfloat16 g_wxt   [XPAD * DINNER];      // W_x^T padded
__device__ __align__(16) __nv_bfloat16 g_xresb [TOK * 2 * DINNER];   // in_proj out
__device__ __align__(16) __nv_bfloat16 g_xcb   [TOK * DINNER];       // conv+silu out
__device__ __align__(16) __nv_bfloat16 g_deltab[TOK * DINNER];       // softplus(dt)
__device__ __align__(16) float g_xdbl [TOK * XPAD];                  // B/C cols used
__device__ __align__(16) float g_xpf  [XKSPLIT * TOK * XPAD];        // x_proj partials
__device__ __align__(16) float g_S    [BATCH * NCHUNK * DN];
__device__ __align__(16) float g_P    [BATCH * NCHUNK * DN];
__device__ __align__(16) float g_SI   [BATCH * NCHUNK * DN];

// ---------------- helpers ----------------
__device__ __forceinline__ float silu_f(float x) {
    return x / (1.f + __expf(-x));
}
__device__ __forceinline__ float ex2f(float x) {
    float r;
    asm("ex2.approx.f32 %0, %1;" : "=f"(r) : "f"(x));
    return r;
}
__device__ __forceinline__ void cp16(uint32_t smem, const void* g) {
    asm volatile("cp.async.cg.shared.global [%0], [%1], 16;\n" :: "r"(smem), "l"(g));
}
__device__ __forceinline__ void mma_bf16(float c[4],
    uint32_t a0, uint32_t a1, uint32_t a2, uint32_t a3,
    uint32_t b0, uint32_t b1) {
    asm volatile(
        "mma.sync.aligned.m16n8k16.row.col.f32.bf16.bf16.f32 "
        "{%0,%1,%2,%3}, {%4,%5,%6,%7}, {%8,%9}, {%0,%1,%2,%3};"
        : "+f"(c[0]), "+f"(c[1]), "+f"(c[2]), "+f"(c[3])
        : "r"(a0), "r"(a1), "r"(a2), "r"(a3), "r"(b0), "r"(b1));
}
__device__ __forceinline__ void ldmx4(uint32_t r[4], uint32_t addr) {
    asm volatile(
        "ldmatrix.sync.aligned.m8n8.x4.shared.b16 {%0,%1,%2,%3}, [%4];"
        : "=r"(r[0]), "=r"(r[1]), "=r"(r[2]), "=r"(r[3]) : "r"(addr));
}

// ---------------- bf16 MMA GEMM, 3-stage pipeline, ONE sync/iter ------------
// CTA tile 128x128, 128 threads (4 warps 2x2), warp tile 64x64.
#define GSTG   16384u
#define NSTAGE 3
#define GEMM_SMEM (2 * NSTAGE * GSTG)     // 96 KB

template <typename OutT>
__global__ void __launch_bounds__(128, 2)
gemm_bf16(const __nv_bfloat16* __restrict__ A, const __nv_bfloat16* __restrict__ Bt,
          OutT* __restrict__ C, int M, int N, int lda, int ldb, int Kslice,
          const float* __restrict__ residual) {
    extern __shared__ char smem[];
    uint32_t smem_base;
    asm("{ .reg .u64 t; cvta.to.shared.u64 t, %1; cvt.u32.u64 %0, t; }"
        : "=r"(smem_base) : "l"(smem));

    int tid  = threadIdx.x;
    int lane = tid & 31, wid = tid >> 5;
    int bm = blockIdx.y * 128, bn = blockIdx.x * 128;
    int wm = (wid >> 1) * 64, wn = (wid & 1) * 64;
    int gid = lane >> 2, tig = lane & 3;
    int koff = blockIdx.z * Kslice;

    float acc[4][8][4];
    #pragma unroll
    for (int i = 0; i < 4; i++)
        #pragma unroll
        for (int j = 0; j < 8; j++)
            #pragma unroll
            for (int q = 0; q < 4; q++) acc[i][j][q] = 0.f;

    const __nv_bfloat16* abase = A + (size_t)bm * lda + koff;
    const __nv_bfloat16* bbase = Bt + (size_t)bn * ldb + koff;
    OutT* Cz = C + (size_t)blockIdx.z * M * N;

    int lrow = tid >> 3;
    int lch  = tid & 7;

    auto load_stage = [&](int s, int kt) {
        uint32_t adst = smem_base + (uint32_t)s * GSTG;
        uint32_t bdst = smem_base + NSTAGE * GSTG + (uint32_t)s * GSTG;
        const __nv_bfloat16* asrc = abase + (size_t)kt * 64;
        const __nv_bfloat16* bsrc = bbase + (size_t)kt * 64;
        #pragma unroll
        for (int u = 0; u < 8; u++) {
            int row = lrow + u * 16;
            uint32_t d = (uint32_t)row * 128 + ((uint32_t)(lch ^ (row & 7)) << 4);
            cp16(adst + d, asrc + (size_t)row * lda + lch * 8);
            cp16(bdst + d, bsrc + (size_t)row * ldb + lch * 8);
        }
        asm volatile("cp.async.commit_group;\n");
    };

    int nt = Kslice / 64;
    load_stage(0, 0);
    load_stage(1, 1);

    for (int t = 0; t < nt; t++) {
        int s = t % NSTAGE;
        if (t + 1 < nt) asm volatile("cp.async.wait_group 1;\n" ::: "memory");
        else            asm volatile("cp.async.wait_group 0;\n" ::: "memory");
        __syncthreads();
        if (t + 2 < nt) load_stage((t + 2) % NSTAGE, t + 2);

        uint32_t abase_s = smem_base + (uint32_t)s * GSTG;
        uint32_t bbase_s = smem_base + NSTAGE * GSTG + (uint32_t)s * GSTG;

        #pragma unroll
        for (int ks = 0; ks < 4; ks++) {
            int k8 = ks * 2;
            uint32_t af[4][4];
            #pragma unroll
            for (int i = 0; i < 4; i++) {
                int row = wm + i * 16 + (lane & 15);
                uint32_t ch = (uint32_t)((k8 + (lane >> 4)) ^ (row & 7));
                ldmx4(af[i], abase_s + (uint32_t)row * 128 + (ch << 4));
            }
            uint32_t b0[8], b1[8];
            #pragma unroll
            for (int h = 0; h < 2; h++) {
                int rowb = wn + h * 32 + lane;
                uint32_t c0 = (uint32_t)((k8    ) ^ (rowb & 7));
                uint32_t c1 = (uint32_t)((k8 + 1) ^ (rowb & 7));
                ldmx4(&b0[h * 4], bbase_s + (uint32_t)rowb * 128 + (c0 << 4));
                ldmx4(&b1[h * 4], bbase_s + (uint32_t)rowb * 128 + (c1 << 4));
            }
            #pragma unroll
            for (int i = 0; i < 4; i++)
                #pragma unroll
                for (int j = 0; j < 8; j++)
                    mma_bf16(acc[i][j], af[i][0], af[i][1], af[i][2], af[i][3],
                             b0[j], b1[j]);
        }
    }

    // ---- epilogue ----
    #pragma unroll
    for (int i = 0; i < 4; i++) {
        int r0 = bm + wm + i * 16 + gid;
        #pragma unroll
        for (int j = 0; j < 8; j++) {
            int c0 = bn + wn + j * 8 + tig * 2;
            float v0 = acc[i][j][0], v1 = acc[i][j][1];
            float v2 = acc[i][j][2], v3 = acc[i][j][3];
            if (residual) {
                const float* rr0 = residual + (size_t)r0 * N + c0;
                const float* rr1 = residual + (size_t)(r0 + 8) * N + c0;
                v0 += rr0[0]; v1 += rr0[1]; v2 += rr1[0]; v3 += rr1[1];
            }
            if constexpr (sizeof(OutT) == 2) {
                __nv_bfloat162 p0 = { __float2bfloat16(v0), __float2bfloat16(v1) };
                __nv_bfloat162 p1 = { __float2bfloat16(v2), __float2bfloat16(v3) };
                *(__nv_bfloat162*)((__nv_bfloat16*)Cz + (size_t)r0 * N + c0)       = p0;
                *(__nv_bfloat162*)((__nv_bfloat16*)Cz + (size_t)(r0 + 8) * N + c0) = p1;
            } else {
                float2 q0 = { v0, v1 }, q1 = { v2, v3 };
                *(float2*)((float*)Cz + (size_t)r0 * N + c0)       = q0;
                *(float2*)((float*)Cz + (size_t)(r0 + 8) * N + c0) = q1;
            }
        }
    }
}

// ---------------- fused prep: rmsnorm + 3 weight transposes ----------------
__device__ __forceinline__ void wtrans_body(const float* __restrict__ W,
                                            __nv_bfloat16* __restrict__ Wt,
                                            int K, int Nsrc, int bx, int by) {
    __shared__ float tile[32][33];
    int tx = threadIdx.x & 31, ty = threadIdx.x >> 5;
    #pragma unroll
    for (int r = 0; r < 32; r += 8) {
        int n = bx + tx;
        tile[ty + r][tx] = (n < Nsrc) ? W[(size_t)(by + ty + r) * Nsrc + n] : 0.f;
    }
    __syncthreads();
    #pragma unroll
    for (int r = 0; r < 32; r += 8)
        Wt[(size_t)(bx + ty + r) * K + by + tx] = __float2bfloat16(tile[tx][ty + r]);
}

__global__ void prep_kernel(const float* __restrict__ x0,
                            const float* __restrict__ norm_w,
                            const float* __restrict__ W_in,
                            const float* __restrict__ W_out,
                            const float* __restrict__ W_x) {
    int bid = blockIdx.x;
    if (bid < TOK) {
        int t = bid;
        const float* xr = x0 + (size_t)t * DMODEL;
        float s = 0.f;
        #pragma unroll
        for (int i = 0; i < DMODEL / 256; i++) {
            float v = xr[threadIdx.x + i * 256];
            s += v * v;
        }
        #pragma unroll
        for (int o = 16; o > 0; o >>= 1) s += __shfl_xor_sync(0xffffffffu, s, o);
        __shared__ float ws[8];
        if ((threadIdx.x & 31) == 0) ws[threadIdx.x >> 5] = s;
        __syncthreads();
        if (threadIdx.x < 8) {
            float v = ws[threadIdx.x];
            #pragma unroll
            for (int o = 4; o > 0; o >>= 1) v += __shfl_xor_sync(0xffu, v, o);
            if (threadIdx.x == 0) ws[0] = v;
        }
        __syncthreads();
        float rs = rsqrtf(ws[0] / (float)DMODEL + EPS);
        __nv_bfloat16* hr = g_hb + (size_t)t * DMODEL;
        #pragma unroll
        for (int i = 0; i < DMODEL / 256; i++) {
            int c = threadIdx.x + i * 256;
            hr[c] = __float2bfloat16(xr[c] * rs * norm_w[c]);
        }
    } else if (bid < TOK + 4096) {
        int t = bid - TOK;
        wtrans_body(W_in, g_wint, DMODEL, 2 * DINNER, (t & 127) * 32, (t >> 7) * 32);
    } else if (bid < TOK + 4096 + 2048) {
        int t = bid - TOK - 4096;
        wtrans_body(W_out, g_woutt, DINNER, DMODEL, (t & 31) * 32, (t >> 5) * 32);
    } else {
        int t = bid - TOK - 4096 - 2048;
        wtrans_body(W_x, g_wxt, DINNER, XDBL_N, (t & 3) * 32, (t >> 2) * 32);
    }
}
#define PREP_BLOCKS (TOK + 4096 + 2048 + 256)

// ---------------- causal depthwise conv (K=4) + SiLU, 8 outputs/thread ------
// Scalar per-d form (independent FMA trees); 11 row loads per 8 outputs.
__global__ void conv_silu_kernel(const float* __restrict__ conv_w,
                                 const float* __restrict__ conv_b) {
    int gidx = blockIdx.x * blockDim.x + threadIdx.x;   // (b, l0/8, d)
    int d  = gidx & (DINNER - 1);
    int q  = gidx >> 11;
    int l8 = q & (LSEQ / 8 - 1);
    int b  = q >> 7;
    int l0 = l8 * 8;

    float w0 = conv_w[d * KCONV + 0];
    float w1 = conv_w[d * KCONV + 1];
    float w2 = conv_w[d * KCONV + 2];
    float w3 = conv_w[d * KCONV + 3];
    float cb = conv_b[d];

    const size_t S = 2 * DINNER;
    const __nv_bfloat16* base = g_xresb + (size_t)(b * LSEQ) * S + d;

    float v[11];
    if (l0 > 0) {
        v[0] = __bfloat162float(base[(size_t)(l0 - 3) * S]);
        v[1] = __bfloat162float(base[(size_t)(l0 - 2) * S]);
        v[2] = __bfloat162float(base[(size_t)(l0 - 1) * S]);
    } else {
        v[0] = v[1] = v[2] = 0.f;
    }
    #pragma unroll
    for (int e = 0; e < 8; e++)
        v[3 + e] = __bfloat162float(base[(size_t)(l0 + e) * S]);

    size_t t0 = (size_t)(b * LSEQ + l0) * DINNER + d;
    #pragma unroll
    for (int e = 0; e < 8; e++) {
        float o = fmaf(w0, v[e], fmaf(w1, v[e+1],
                  fmaf(w2, v[e+2], fmaf(w3, v[e+3], cb))));
        g_xcb[t0 + (size_t)e * DINNER] = __float2bfloat16(silu_f(o));
    }
}

// ---------------- fused x_proj reduce + delta GEMM ----------------
__global__ void __launch_bounds__(512)
delta_fused_kernel(const float* __restrict__ W_dt,
                   const float* __restrict__ b_dt) {
    __shared__ float sd[16][DTRANK];
    int tid = threadIdx.x;
    int t0 = blockIdx.x * 16;

    {
        int tok  = tid >> 5;
        int col4 = tid & 31;
        int off = (t0 + tok) * (XPAD / 4) + col4;
        float4 s = { 0.f, 0.f, 0.f, 0.f };
        #pragma unroll
        for (int q = 0; q < XKSPLIT; q++) {
            float4 v = *((const float4*)(g_xpf + (size_t)q * TOK * XPAD) + off);
            s.x += v.x; s.y += v.y; s.z += v.z; s.w += v.w;
        }
        if (col4 < 16) {
            *(float4*)&sd[tok][col4 * 4] = s;
        } else {
            *((float4*)g_xdbl + off) = s;
        }
    }
    __syncthreads();

    float bb[4];
    #pragma unroll
    for (int j = 0; j < 4; j++) bb[j] = b_dt[tid + 512 * j];
    float acc[16][4];
    #pragma unroll
    for (int tok = 0; tok < 16; tok++)
        #pragma unroll
        for (int j = 0; j < 4; j++) acc[tok][j] = bb[j];

    #pragma unroll 4
    for (int k = 0; k < DTRANK; k++) {
        float w[4];
        #pragma unroll
        for (int j = 0; j < 4; j++)
            w[j] = W_dt[(size_t)k * DINNER + tid + 512 * j];
        #pragma unroll
        for (int tok = 0; tok < 16; tok++) {
            float dl = sd[tok][k];
            #pragma unroll
            for (int j = 0; j < 4; j++) acc[tok][j] = fmaf(dl, w[j], acc[tok][j]);
        }
    }
    #pragma unroll
    for (int tok = 0; tok < 16; tok++)
        #pragma unroll
        for (int j = 0; j < 4; j++) {
            float x = acc[tok][j];
            float sp = (x > 20.f) ? x : log1pf(__expf(x));
            g_deltab[(size_t)(t0 + tok) * DINNER + tid + 512 * j] =
                __float2bfloat16(sp);
        }
}

// ---------------- scan pass A ----------------
__global__ void scanA_kernel(const float* __restrict__ A) {
    int g = blockIdx.x * blockDim.x + threadIdx.x;
    int tid = threadIdx.x;
    int d  = g & (DINNER - 1);
    int bc = g >> 11;
    int c  = bc & (NCHUNK - 1);
    int b  = bc >> 5;
    int t0 = b * LSEQ + c * CLEN;

    __shared__ float sB[CLEN][DSTATE];
    {
        int l = tid >> 3, n2 = tid & 7;
        float2 v = *(const float2*)(g_xdbl + (size_t)(t0 + l) * XPAD + DTRANK + n2 * 2);
        *(float2*)&sB[l][n2 * 2] = v;
    }
    __syncthreads();

    float a[DSTATE], s[DSTATE], P[DSTATE];
    #pragma unroll
    for (int q = 0; q < 4; q++) {
        float4 v = *(const float4*)(A + d * DSTATE + q * 4);
        a[q*4+0]=v.x*LOG2E; a[q*4+1]=v.y*LOG2E; a[q*4+2]=v.z*LOG2E; a[q*4+3]=v.w*LOG2E;
    }
    #pragma unroll
    for (int n = 0; n < DSTATE; n++) { s[n] = 0.f; P[n] = 1.f; }

    for (int l = 0; l < CLEN; l++) {
        int t = t0 + l;
        float delta = __bfloat162float(g_deltab[(size_t)t * DINNER + d]);
        float xv    = __bfloat162float(g_xcb   [(size_t)t * DINNER + d]);
        float du    = delta * xv;
        #pragma unroll
        for (int n = 0; n < DSTATE; n++) {
            float dA = ex2f(delta * a[n]);
            s[n] = fmaf(dA, s[n], du * sB[l][n]);
            P[n] *= dA;
        }
    }
    float* Sp = g_S + (size_t)bc * DN + d * DSTATE;
    float* Pp = g_P + (size_t)bc * DN + d * DSTATE;
    #pragma unroll
    for (int q = 0; q < 4; q++) {
        float4 vs = { s[q*4+0], s[q*4+1], s[q*4+2], s[q*4+3] };
        float4 vp = { P[q*4+0], P[q*4+1], P[q*4+2], P[q*4+3] };
        *(float4*)(Sp + q * 4) = vs;
        *(float4*)(Pp + q * 4) = vp;
    }
}

// ---------------- scan pass B ----------------
__global__ void scanB_kernel() {
    int g = blockIdx.x * blockDim.x + threadIdx.x;
    int per_b = DN / 4;
    int b   = g / per_b;
    int i4  = g - b * per_b;
    const float4* S4  = (const float4*)g_S;
    const float4* P4  = (const float4*)g_P;
    float4*       SI4 = (float4*)g_SI;
    size_t base = (size_t)b * NCHUNK * per_b + i4;
    float4 s = { 0.f, 0.f, 0.f, 0.f };
    #pragma unroll 4
    for (int c = 0; c < NCHUNK; c++) {
        size_t o = base + (size_t)c * per_b;
        SI4[o] = s;
        float4 sv = S4[o], pv = P4[o];
        s.x = fmaf(pv.x, s.x, sv.x);
        s.y = fmaf(pv.y, s.y, sv.y);
        s.z = fmaf(pv.z, s.z, sv.z);
        s.w = fmaf(pv.w, s.w, sv.w);
    }
}

// ---------------- scan pass C ----------------
__global__ void scanC_kernel(const float* __restrict__ A,
                             const float* __restrict__ Dp) {
    int g = blockIdx.x * blockDim.x + threadIdx.x;
    int tid = threadIdx.x;
    int d  = g & (DINNER - 1);
    int bc = g >> 11;
    int c  = bc & (NCHUNK - 1);
    int b  = bc >> 5;
    int t0 = b * LSEQ + c * CLEN;

    __shared__ float sB[CLEN][DSTATE];
    __shared__ float sC[CLEN][DSTATE];
    {
        int l = tid >> 3, n2 = tid & 7;
        const float* row = g_xdbl + (size_t)(t0 + l) * XPAD + DTRANK;
        *(float2*)&sB[l][n2 * 2] = *(const float2*)(row + n2 * 2);
        *(float2*)&sC[l][n2 * 2] = *(const float2*)(row + DSTATE + n2 * 2);
    }
    __syncthreads();

    float a[DSTATE], s[DSTATE];
    #pragma unroll
    for (int q = 0; q < 4; q++) {
        float4 v = *(const float4*)(A + d * DSTATE + q * 4);
        a[q*4+0]=v.x*LOG2E; a[q*4+1]=v.y*LOG2E; a[q*4+2]=v.z*LOG2E; a[q*4+3]=v.w*LOG2E;
        float4 vi = *(const float4*)(g_SI + (size_t)bc * DN + d * DSTATE + q * 4);
        s[q*4+0]=vi.x; s[q*4+1]=vi.y; s[q*4+2]=vi.z; s[q*4+3]=vi.w;
    }
    float Dd = Dp[d];

    for (int l = 0; l < CLEN; l++) {
        int t = t0 + l;
        float delta = __bfloat162float(g_deltab[(size_t)t * DINNER + d]);
        float xv    = __bfloat162float(g_xcb   [(size_t)t * DINNER + d]);
        float du    = delta * xv;
        float y = 0.f;
        #pragma unroll
        for (int n = 0; n < DSTATE; n++) {
            float dA = ex2f(delta * a[n]);
            s[n] = fmaf(dA, s[n], du * sB[l][n]);
            y = fmaf(s[n], sC[l][n], y);
        }
        float res = __bfloat162float(
            g_xresb[(size_t)t * (2 * DINNER) + DINNER + d]);
        g_yb[(size_t)t * DINNER + d] =
            __float2bfloat16((y + xv * Dd) * silu_f(res));
    }
}

// ---------------- launch ----------------
extern "C" void kernel_launch(void* const* d_in, const int* in_sizes, int n_in,
                              void* d_out, int out_size) {
    const float* x0     = (const float*)d_in[0];
    const float* norm_w = (const float*)d_in[1];
    const float* W_in   = (const float*)d_in[2];
    const float* conv_w = (const float*)d_in[3];
    const float* conv_b = (const float*)d_in[4];
    const float* W_x    = (const float*)d_in[5];
    const float* W_dt   = (const float*)d_in[6];
    const float* b_dt   = (const float*)d_in[7];
    const float* Amat   = (const float*)d_in[8];
    const float* Dvec   = (const float*)d_in[9];
    const float* W_out  = (const float*)d_in[10];
    float* out = (float*)d_out;

    __nv_bfloat16 *p_hb, *p_yb, *p_wint, *p_woutt, *p_wxt, *p_xresb, *p_xcb;
    float *p_xpf;
    cudaGetSymbolAddress((void**)&p_hb,    g_hb);
    cudaGetSymbolAddress((void**)&p_yb,    g_yb);
    cudaGetSymbolAddress((void**)&p_wint,  g_wint);
    cudaGetSymbolAddress((void**)&p_woutt, g_woutt);
    cudaGetSymbolAddress((void**)&p_wxt,   g_wxt);
    cudaGetSymbolAddress((void**)&p_xresb, g_xresb);
    cudaGetSymbolAddress((void**)&p_xcb,   g_xcb);
    cudaGetSymbolAddress((void**)&p_xpf,   g_xpf);

    cudaFuncSetAttribute(gemm_bf16<__nv_bfloat16>,
                         cudaFuncAttributeMaxDynamicSharedMemorySize, GEMM_SMEM);
    cudaFuncSetAttribute(gemm_bf16<float>,
                         cudaFuncAttributeMaxDynamicSharedMemorySize, GEMM_SMEM);

    // 1) fused prep: rmsnorm + all weight transposes
    prep_kernel<<<PREP_BLOCKS, 256>>>(x0, norm_w, W_in, W_out, W_x);

    // 2) in_proj (bf16 mma, bf16 out): [2048,1024] @ [1024,4096]
    gemm_bf16<__nv_bfloat16><<<dim3((2 * DINNER) / 128, TOK / 128), 128, GEMM_SMEM>>>(
        p_hb, p_wint, p_xresb, TOK, 2 * DINNER, DMODEL, DMODEL, DMODEL, nullptr);

    // 3) conv + silu (scalar, 8 outputs/thread)
    conv_silu_kernel<<<(TOK / 8 * DINNER) / 256, 256>>>(conv_w, conv_b);

    // 4) x_proj: split-K bf16 mma -> partials
    gemm_bf16<float><<<dim3(1, TOK / 128, XKSPLIT), 128, GEMM_SMEM>>>(
        p_xcb, p_wxt, p_xpf, TOK, XPAD, DINNER, DINNER, DINNER / XKSPLIT, nullptr);

    // 5) fused reduce + delta
    delta_fused_kernel<<<TOK / 16, 512>>>(W_dt, b_dt);

    // 6) chunked selective scan
    scanA_kernel<<<(BATCH * NCHUNK * DINNER) / 256, 256>>>(Amat);
    scanB_kernel<<<(BATCH * DN / 4) / 256, 256>>>();
    scanC_kernel<<<(BATCH * NCHUNK * DINNER) / 256, 256>>>(Amat, Dvec);

    // 7) out_proj (bf16 mma, fp32 out) + residual: [2048,2048] @ [2048,1024]
    gemm_bf16<float><<<dim3(DMODEL / 128, TOK / 128), 128, GEMM_SMEM>>>(
        p_yb, p_woutt, out, TOK, DMODEL, DINNER, DINNER, DINNER, x0);
}

// round 16
// speedup vs baseline: 1.0495x; 1.0246x over previous
#include <cuda_runtime.h>
#include <cuda_bf16.h>
#include <math.h>
#include <stdint.h>

// ---------------- problem constants ----------------
#define BATCH   2
#define LSEQ    1024
#define DMODEL  1024
#define DINNER  2048
#define DSTATE  16
#define DTRANK  64
#define KCONV   4
#define TOK     (BATCH*LSEQ)        // 2048 tokens
#define XDBL_N  96
#define XPAD    128                 // padded xdbl stride
#define EPS     1e-5f
#define LOG2E   1.44269504088896f

#define NCHUNK  32
#define CLEN    (LSEQ/NCHUNK)       // 32
#define DN      (DINNER*DSTATE)     // 32768
#define XKSPLIT 16                  // x_proj K splits (MMA)

// ---------------- scratch ----------------
__device__ __align__(16) __nv_bfloat16 g_hb    [TOK * DMODEL];       // rmsnorm out
__device__ __align__(16) __nv_bfloat16 g_yb    [TOK * DINNER];       // scan out
__device__ __align__(16) __nv_bfloat16 g_wint  [2*DINNER * DMODEL];  // W_in^T
__device__ __align__(16) __nv_bfloat16 g_woutt [DMODEL * DINNER];    // W_out^T
__device__ __align__(16) __nv_bfloat16 g_wxt   [XPAD * DINNER];      // W_x^T padded
__device__ __align__(16) __nv_bfloat16 g_xresb [TOK * 2 * DINNER];   // in_proj out
__device__ __align__(16) __nv_bfloat16 g_xcb   [TOK * DINNER];       // conv+silu out
__device__ __align__(16) __nv_bfloat16 g_deltab[TOK * DINNER];       // softplus(dt)
__device__ __align__(16) float g_xdbl [TOK * XPAD];                  // B/C cols used
__device__ __align__(16) float g_xpf  [XKSPLIT * TOK * XPAD];        // x_proj partials
__device__ __align__(16) float g_S    [BATCH * NCHUNK * DN];
__device__ __align__(16) float g_P    [BATCH * NCHUNK * DN];
__device__ __align__(16) float g_SI   [BATCH * NCHUNK * DN];

// ---------------- helpers ----------------
__device__ __forceinline__ float silu_f(float x) {
    return x / (1.f + __expf(-x));
}
__device__ __forceinline__ float ex2f(float x) {
    float r;
    asm("ex2.approx.f32 %0, %1;" : "=f"(r) : "f"(x));
    return r;
}
__device__ __forceinline__ void cp16(uint32_t smem, const void* g) {
    asm volatile("cp.async.cg.shared.global [%0], [%1], 16;\n" :: "r"(smem), "l"(g));
}
__device__ __forceinline__ void mma_bf16(float c[4],
    uint32_t a0, uint32_t a1, uint32_t a2, uint32_t a3,
    uint32_t b0, uint32_t b1) {
    asm volatile(
        "mma.sync.aligned.m16n8k16.row.col.f32.bf16.bf16.f32 "
        "{%0,%1,%2,%3}, {%4,%5,%6,%7}, {%8,%9}, {%0,%1,%2,%3};"
        : "+f"(c[0]), "+f"(c[1]), "+f"(c[2]), "+f"(c[3])
        : "r"(a0), "r"(a1), "r"(a2), "r"(a3), "r"(b0), "r"(b1));
}
__device__ __forceinline__ void ldmx4(uint32_t r[4], uint32_t addr) {
    asm volatile(
        "ldmatrix.sync.aligned.m8n8.x4.shared.b16 {%0,%1,%2,%3}, [%4];"
        : "=r"(r[0]), "=r"(r[1]), "=r"(r[2]), "=r"(r[3]) : "r"(addr));
}

// ---------------- bf16 MMA GEMM, 3-stage pipeline, ONE sync/iter ------------
// CTA tile 128x128, 128 threads (4 warps 2x2), warp tile 64x64.
#define GSTG   16384u
#define NSTAGE 3
#define GEMM_SMEM (2 * NSTAGE * GSTG)     // 96 KB

template <typename OutT>
__global__ void __launch_bounds__(128, 2)
gemm_bf16(const __nv_bfloat16* __restrict__ A, const __nv_bfloat16* __restrict__ Bt,
          OutT* __restrict__ C, int M, int N, int lda, int ldb, int Kslice,
          const float* __restrict__ residual) {
    extern __shared__ char smem[];
    uint32_t smem_base;
    asm("{ .reg .u64 t; cvta.to.shared.u64 t, %1; cvt.u32.u64 %0, t; }"
        : "=r"(smem_base) : "l"(smem));

    int tid  = threadIdx.x;
    int lane = tid & 31, wid = tid >> 5;
    int bm = blockIdx.y * 128, bn = blockIdx.x * 128;
    int wm = (wid >> 1) * 64, wn = (wid & 1) * 64;
    int gid = lane >> 2, tig = lane & 3;
    int koff = blockIdx.z * Kslice;

    float acc[4][8][4];
    #pragma unroll
    for (int i = 0; i < 4; i++)
        #pragma unroll
        for (int j = 0; j < 8; j++)
            #pragma unroll
            for (int q = 0; q < 4; q++) acc[i][j][q] = 0.f;

    const __nv_bfloat16* abase = A + (size_t)bm * lda + koff;
    const __nv_bfloat16* bbase = Bt + (size_t)bn * ldb + koff;
    OutT* Cz = C + (size_t)blockIdx.z * M * N;

    int lrow = tid >> 3;
    int lch  = tid & 7;

    auto load_stage = [&](int s, int kt) {
        uint32_t adst = smem_base + (uint32_t)s * GSTG;
        uint32_t bdst = smem_base + NSTAGE * GSTG + (uint32_t)s * GSTG;
        const __nv_bfloat16* asrc = abase + (size_t)kt * 64;
        const __nv_bfloat16* bsrc = bbase + (size_t)kt * 64;
        #pragma unroll
        for (int u = 0; u < 8; u++) {
            int row = lrow + u * 16;
            uint32_t d = (uint32_t)row * 128 + ((uint32_t)(lch ^ (row & 7)) << 4);
            cp16(adst + d, asrc + (size_t)row * lda + lch * 8);
            cp16(bdst + d, bsrc + (size_t)row * ldb + lch * 8);
        }
        asm volatile("cp.async.commit_group;\n");
    };

    int nt = Kslice / 64;
    load_stage(0, 0);
    load_stage(1, 1);

    for (int t = 0; t < nt; t++) {
        int s = t % NSTAGE;
        if (t + 1 < nt) asm volatile("cp.async.wait_group 1;\n" ::: "memory");
        else            asm volatile("cp.async.wait_group 0;\n" ::: "memory");
        __syncthreads();
        if (t + 2 < nt) load_stage((t + 2) % NSTAGE, t + 2);

        uint32_t abase_s = smem_base + (uint32_t)s * GSTG;
        uint32_t bbase_s = smem_base + NSTAGE * GSTG + (uint32_t)s * GSTG;

        #pragma unroll
        for (int ks = 0; ks < 4; ks++) {
            int k8 = ks * 2;
            uint32_t af[4][4];
            #pragma unroll
            for (int i = 0; i < 4; i++) {
                int row = wm + i * 16 + (lane & 15);
                uint32_t ch = (uint32_t)((k8 + (lane >> 4)) ^ (row & 7));
                ldmx4(af[i], abase_s + (uint32_t)row * 128 + (ch << 4));
            }
            uint32_t b0[8], b1[8];
            #pragma unroll
            for (int h = 0; h < 2; h++) {
                int rowb = wn + h * 32 + lane;
                uint32_t c0 = (uint32_t)((k8    ) ^ (rowb & 7));
                uint32_t c1 = (uint32_t)((k8 + 1) ^ (rowb & 7));
                ldmx4(&b0[h * 4], bbase_s + (uint32_t)rowb * 128 + (c0 << 4));
                ldmx4(&b1[h * 4], bbase_s + (uint32_t)rowb * 128 + (c1 << 4));
            }
            #pragma unroll
            for (int i = 0; i < 4; i++)
                #pragma unroll
                for (int j = 0; j < 8; j++)
                    mma_bf16(acc[i][j], af[i][0], af[i][1], af[i][2], af[i][3],
                             b0[j], b1[j]);
        }
    }

    // ---- epilogue ----
    #pragma unroll
    for (int i = 0; i < 4; i++) {
        int r0 = bm + wm + i * 16 + gid;
        #pragma unroll
        for (int j = 0; j < 8; j++) {
            int c0 = bn + wn + j * 8 + tig * 2;
            float v0 = acc[i][j][0], v1 = acc[i][j][1];
            float v2 = acc[i][j][2], v3 = acc[i][j][3];
            if (residual) {
                const float* rr0 = residual + (size_t)r0 * N + c0;
                const float* rr1 = residual + (size_t)(r0 + 8) * N + c0;
                v0 += rr0[0]; v1 += rr0[1]; v2 += rr1[0]; v3 += rr1[1];
            }
            if constexpr (sizeof(OutT) == 2) {
                __nv_bfloat162 p0 = { __float2bfloat16(v0), __float2bfloat16(v1) };
                __nv_bfloat162 p1 = { __float2bfloat16(v2), __float2bfloat16(v3) };
                *(__nv_bfloat162*)((__nv_bfloat16*)Cz + (size_t)r0 * N + c0)       = p0;
                *(__nv_bfloat162*)((__nv_bfloat16*)Cz + (size_t)(r0 + 8) * N + c0) = p1;
            } else {
                float2 q0 = { v0, v1 }, q1 = { v2, v3 };
                *(float2*)((float*)Cz + (size_t)r0 * N + c0)       = q0;
                *(float2*)((float*)Cz + (size_t)(r0 + 8) * N + c0) = q1;
            }
        }
    }
}

// ---------------- fused prep: rmsnorm + 3 weight transposes ----------------
__device__ __forceinline__ void wtrans_body(const float* __restrict__ W,
                                            __nv_bfloat16* __restrict__ Wt,
                                            int K, int Nsrc, int bx, int by) {
    __shared__ float tile[32][33];
    int tx = threadIdx.x & 31, ty = threadIdx.x >> 5;
    #pragma unroll
    for (int r = 0; r < 32; r += 8) {
        int n = bx + tx;
        tile[ty + r][tx] = (n < Nsrc) ? W[(size_t)(by + ty + r) * Nsrc + n] : 0.f;
    }
    __syncthreads();
    #pragma unroll
    for (int r = 0; r < 32; r += 8)
        Wt[(size_t)(bx + ty + r) * K + by + tx] = __float2bfloat16(tile[tx][ty + r]);
}

__global__ void prep_kernel(const float* __restrict__ x0,
                            const float* __restrict__ norm_w,
                            const float* __restrict__ W_in,
                            const float* __restrict__ W_out,
                            const float* __restrict__ W_x) {
    int bid = blockIdx.x;
    if (bid < TOK) {
        int t = bid;
        const float* xr = x0 + (size_t)t * DMODEL;
        float s = 0.f;
        #pragma unroll
        for (int i = 0; i < DMODEL / 256; i++) {
            float v = xr[threadIdx.x + i * 256];
            s += v * v;
        }
        #pragma unroll
        for (int o = 16; o > 0; o >>= 1) s += __shfl_xor_sync(0xffffffffu, s, o);
        __shared__ float ws[8];
        if ((threadIdx.x & 31) == 0) ws[threadIdx.x >> 5] = s;
        __syncthreads();
        if (threadIdx.x < 8) {
            float v = ws[threadIdx.x];
            #pragma unroll
            for (int o = 4; o > 0; o >>= 1) v += __shfl_xor_sync(0xffu, v, o);
            if (threadIdx.x == 0) ws[0] = v;
        }
        __syncthreads();
        float rs = rsqrtf(ws[0] / (float)DMODEL + EPS);
        __nv_bfloat16* hr = g_hb + (size_t)t * DMODEL;
        #pragma unroll
        for (int i = 0; i < DMODEL / 256; i++) {
            int c = threadIdx.x + i * 256;
            hr[c] = __float2bfloat16(xr[c] * rs * norm_w[c]);
        }
    } else if (bid < TOK + 4096) {
        int t = bid - TOK;
        wtrans_body(W_in, g_wint, DMODEL, 2 * DINNER, (t & 127) * 32, (t >> 7) * 32);
    } else if (bid < TOK + 4096 + 2048) {
        int t = bid - TOK - 4096;
        wtrans_body(W_out, g_woutt, DINNER, DMODEL, (t & 31) * 32, (t >> 5) * 32);
    } else {
        int t = bid - TOK - 4096 - 2048;
        wtrans_body(W_x, g_wxt, DINNER, XDBL_N, (t & 3) * 32, (t >> 2) * 32);
    }
}
#define PREP_BLOCKS (TOK + 4096 + 2048 + 256)

// ---------------- causal depthwise conv (K=4) + SiLU, 8 outputs/thread ------
__global__ void conv_silu_kernel(const float* __restrict__ conv_w,
                                 const float* __restrict__ conv_b) {
    int gidx = blockIdx.x * blockDim.x + threadIdx.x;   // (b, l0/8, d)
    int d  = gidx & (DINNER - 1);
    int q  = gidx >> 11;
    int l8 = q & (LSEQ / 8 - 1);
    int b  = q >> 7;
    int l0 = l8 * 8;

    float w0 = conv_w[d * KCONV + 0];
    float w1 = conv_w[d * KCONV + 1];
    float w2 = conv_w[d * KCONV + 2];
    float w3 = conv_w[d * KCONV + 3];
    float cb = conv_b[d];

    const size_t S = 2 * DINNER;
    const __nv_bfloat16* base = g_xresb + (size_t)(b * LSEQ) * S + d;

    float v[11];
    if (l0 > 0) {
        v[0] = __bfloat162float(base[(size_t)(l0 - 3) * S]);
        v[1] = __bfloat162float(base[(size_t)(l0 - 2) * S]);
        v[2] = __bfloat162float(base[(size_t)(l0 - 1) * S]);
    } else {
        v[0] = v[1] = v[2] = 0.f;
    }
    #pragma unroll
    for (int e = 0; e < 8; e++)
        v[3 + e] = __bfloat162float(base[(size_t)(l0 + e) * S]);

    size_t t0 = (size_t)(b * LSEQ + l0) * DINNER + d;
    #pragma unroll
    for (int e = 0; e < 8; e++) {
        float o = fmaf(w0, v[e], fmaf(w1, v[e+1],
                  fmaf(w2, v[e+2], fmaf(w3, v[e+3], cb))));
        g_xcb[t0 + (size_t)e * DINNER] = __float2bfloat16(silu_f(o));
    }
}

// ---------------- fused x_proj reduce + delta GEMM ----------------
__global__ void __launch_bounds__(512)
delta_fused_kernel(const float* __restrict__ W_dt,
                   const float* __restrict__ b_dt) {
    __shared__ float sd[16][DTRANK];
    int tid = threadIdx.x;
    int t0 = blockIdx.x * 16;

    {
        int tok  = tid >> 5;
        int col4 = tid & 31;
        int off = (t0 + tok) * (XPAD / 4) + col4;
        float4 s = { 0.f, 0.f, 0.f, 0.f };
        #pragma unroll
        for (int q = 0; q < XKSPLIT; q++) {
            float4 v = *((const float4*)(g_xpf + (size_t)q * TOK * XPAD) + off);
            s.x += v.x; s.y += v.y; s.z += v.z; s.w += v.w;
        }
        if (col4 < 16) {
            *(float4*)&sd[tok][col4 * 4] = s;
        } else {
            *((float4*)g_xdbl + off) = s;
        }
    }
    __syncthreads();

    float bb[4];
    #pragma unroll
    for (int j = 0; j < 4; j++) bb[j] = b_dt[tid + 512 * j];
    float acc[16][4];
    #pragma unroll
    for (int tok = 0; tok < 16; tok++)
        #pragma unroll
        for (int j = 0; j < 4; j++) acc[tok][j] = bb[j];

    #pragma unroll 4
    for (int k = 0; k < DTRANK; k++) {
        float w[4];
        #pragma unroll
        for (int j = 0; j < 4; j++)
            w[j] = W_dt[(size_t)k * DINNER + tid + 512 * j];
        #pragma unroll
        for (int tok = 0; tok < 16; tok++) {
            float dl = sd[tok][k];
            #pragma unroll
            for (int j = 0; j < 4; j++) acc[tok][j] = fmaf(dl, w[j], acc[tok][j]);
        }
    }
    #pragma unroll
    for (int tok = 0; tok < 16; tok++)
        #pragma unroll
        for (int j = 0; j < 4; j++) {
            float x = acc[tok][j];
            float sp = (x > 20.f) ? x : log1pf(__expf(x));
            g_deltab[(size_t)(t0 + tok) * DINNER + tid + 512 * j] =
                __float2bfloat16(sp);
        }
}

// ---------------- scan pass A ----------------
__global__ void scanA_kernel(const float* __restrict__ A) {
    int g = blockIdx.x * blockDim.x + threadIdx.x;
    int tid = threadIdx.x;
    int d  = g & (DINNER - 1);
    int bc = g >> 11;
    int c  = bc & (NCHUNK - 1);
    int b  = bc >> 5;
    int t0 = b * LSEQ + c * CLEN;

    __shared__ float sB[CLEN][DSTATE];
    {
        int l = tid >> 3, n2 = tid & 7;
        float2 v = *(const float2*)(g_xdbl + (size_t)(t0 + l) * XPAD + DTRANK + n2 * 2);
        *(float2*)&sB[l][n2 * 2] = v;
    }
    __syncthreads();

    float a[DSTATE], s[DSTATE], P[DSTATE];
    #pragma unroll
    for (int q = 0; q < 4; q++) {
        float4 v = *(const float4*)(A + d * DSTATE + q * 4);
        a[q*4+0]=v.x*LOG2E; a[q*4+1]=v.y*LOG2E; a[q*4+2]=v.z*LOG2E; a[q*4+3]=v.w*LOG2E;
    }
    #pragma unroll
    for (int n = 0; n < DSTATE; n++) { s[n] = 0.f; P[n] = 1.f; }

    for (int l = 0; l < CLEN; l++) {
        int t = t0 + l;
        float delta = __bfloat162float(g_deltab[(size_t)t * DINNER + d]);
        float xv    = __bfloat162float(g_xcb   [(size_t)t * DINNER + d]);
        float du    = delta * xv;
        #pragma unroll
        for (int n = 0; n < DSTATE; n++) {
            float dA = ex2f(delta * a[n]);
            s[n] = fmaf(dA, s[n], du * sB[l][n]);
            P[n] *= dA;
        }
    }
    float* Sp = g_S + (size_t)bc * DN + d * DSTATE;
    float* Pp = g_P + (size_t)bc * DN + d * DSTATE;
    #pragma unroll
    for (int q = 0; q < 4; q++) {
        float4 vs = { s[q*4+0], s[q*4+1], s[q*4+2], s[q*4+3] };
        float4 vp = { P[q*4+0], P[q*4+1], P[q*4+2], P[q*4+3] };
        *(float4*)(Sp + q * 4) = vs;
        *(float4*)(Pp + q * 4) = vp;
    }
}

// ---------------- scan pass B ----------------
__global__ void scanB_kernel() {
    int g = blockIdx.x * blockDim.x + threadIdx.x;
    int per_b = DN / 4;
    int b   = g / per_b;
    int i4  = g - b * per_b;
    const float4* S4  = (const float4*)g_S;
    const float4* P4  = (const float4*)g_P;
    float4*       SI4 = (float4*)g_SI;
    size_t base = (size_t)b * NCHUNK * per_b + i4;
    float4 s = { 0.f, 0.f, 0.f, 0.f };
    #pragma unroll 4
    for (int c = 0; c < NCHUNK; c++) {
        size_t o = base + (size_t)c * per_b;
        SI4[o] = s;
        float4 sv = S4[o], pv = P4[o];
        s.x = fmaf(pv.x, s.x, sv.x);
        s.y = fmaf(pv.y, s.y, sv.y);
        s.z = fmaf(pv.z, s.z, sv.z);
        s.w = fmaf(pv.w, s.w, sv.w);
    }
}

// ---------------- scan pass C ----------------
__global__ void scanC_kernel(const float* __restrict__ A,
                             const float* __restrict__ Dp) {
    int g = blockIdx.x * blockDim.x + threadIdx.x;
    int tid = threadIdx.x;
    int d  = g & (DINNER - 1);
    int bc = g >> 11;
    int c  = bc & (NCHUNK - 1);
    int b  = bc >> 5;
    int t0 = b * LSEQ + c * CLEN;

    __shared__ float sB[CLEN][DSTATE];
    __shared__ float sC[CLEN][DSTATE];
    {
        int l = tid >> 3, n2 = tid & 7;
        const float* row = g_xdbl + (size_t)(t0 + l) * XPAD + DTRANK;
        *(float2*)&sB[l][n2 * 2] = *(const float2*)(row + n2 * 2);
        *(float2*)&sC[l][n2 * 2] = *(const float2*)(row + DSTATE + n2 * 2);
    }
    __syncthreads();

    float a[DSTATE], s[DSTATE];
    #pragma unroll
    for (int q = 0; q < 4; q++) {
        float4 v = *(const float4*)(A + d * DSTATE + q * 4);
        a[q*4+0]=v.x*LOG2E; a[q*4+1]=v.y*LOG2E; a[q*4+2]=v.z*LOG2E; a[q*4+3]=v.w*LOG2E;
        float4 vi = *(const float4*)(g_SI + (size_t)bc * DN + d * DSTATE + q * 4);
        s[q*4+0]=vi.x; s[q*4+1]=vi.y; s[q*4+2]=vi.z; s[q*4+3]=vi.w;
    }
    float Dd = Dp[d];

    for (int l = 0; l < CLEN; l++) {
        int t = t0 + l;
        float delta = __bfloat162float(g_deltab[(size_t)t * DINNER + d]);
        float xv    = __bfloat162float(g_xcb   [(size_t)t * DINNER + d]);
        float du    = delta * xv;
        float y = 0.f;
        #pragma unroll
        for (int n = 0; n < DSTATE; n++) {
            float dA = ex2f(delta * a[n]);
            s[n] = fmaf(dA, s[n], du * sB[l][n]);
            y = fmaf(s[n], sC[l][n], y);
        }
        float res = __bfloat162float(
            g_xresb[(size_t)t * (2 * DINNER) + DINNER + d]);
        g_yb[(size_t)t * DINNER + d] =
            __float2bfloat16((y + xv * Dd) * silu_f(res));
    }
}

// ---------------- launch ----------------
extern "C" void kernel_launch(void* const* d_in, const int* in_sizes, int n_in,
                              void* d_out, int out_size) {
    const float* x0     = (const float*)d_in[0];
    const float* norm_w = (const float*)d_in[1];
    const float* W_in   = (const float*)d_in[2];
    const float* conv_w = (const float*)d_in[3];
    const float* conv_b = (const float*)d_in[4];
    const float* W_x    = (const float*)d_in[5];
    const float* W_dt   = (const float*)d_in[6];
    const float* b_dt   = (const float*)d_in[7];
    const float* Amat   = (const float*)d_in[8];
    const float* Dvec   = (const float*)d_in[9];
    const float* W_out  = (const float*)d_in[10];
    float* out = (float*)d_out;

    __nv_bfloat16 *p_hb, *p_yb, *p_wint, *p_woutt, *p_wxt, *p_xresb, *p_xcb;
    float *p_xpf;
    cudaGetSymbolAddress((void**)&p_hb,    g_hb);
    cudaGetSymbolAddress((void**)&p_yb,    g_yb);
    cudaGetSymbolAddress((void**)&p_wint,  g_wint);
    cudaGetSymbolAddress((void**)&p_woutt, g_woutt);
    cudaGetSymbolAddress((void**)&p_wxt,   g_wxt);
    cudaGetSymbolAddress((void**)&p_xresb, g_xresb);
    cudaGetSymbolAddress((void**)&p_xcb,   g_xcb);
    cudaGetSymbolAddress((void**)&p_xpf,   g_xpf);

    cudaFuncSetAttribute(gemm_bf16<__nv_bfloat16>,
                         cudaFuncAttributeMaxDynamicSharedMemorySize, GEMM_SMEM);
    cudaFuncSetAttribute(gemm_bf16<float>,
                         cudaFuncAttributeMaxDynamicSharedMemorySize, GEMM_SMEM);

    // one-time side-stream + events (created on first, non-captured call)
    static cudaStream_t s2 = nullptr;
    static cudaEvent_t evFork = nullptr, evJoin = nullptr;
    if (!s2) {
        cudaStreamCreateWithFlags(&s2, cudaStreamNonBlocking);
        cudaEventCreateWithFlags(&evFork, cudaEventDisableTiming);
        cudaEventCreateWithFlags(&evJoin, cudaEventDisableTiming);
    }

    // 1) fused prep: rmsnorm + all weight transposes (stream 0)
    prep_kernel<<<PREP_BLOCKS, 256>>>(x0, norm_w, W_in, W_out, W_x);

    // 2a) in_proj x-half (cols [0,2048)) on stream 0
    gemm_bf16<__nv_bfloat16><<<dim3(DINNER / 128, TOK / 128), 128, GEMM_SMEM>>>(
        p_hb, p_wint, p_xresb, TOK, 2 * DINNER, DMODEL, DMODEL, DMODEL, nullptr);

    // fork: res-half (cols [2048,4096)) on side stream, overlapped with
    // conv/xproj/delta/scanA/scanB (none of which read the res half)
    cudaEventRecord(evFork, 0);
    cudaStreamWaitEvent(s2, evFork, 0);
    gemm_bf16<__nv_bfloat16>
        <<<dim3(DINNER / 128, TOK / 128), 128, GEMM_SMEM, s2>>>(
        p_hb, p_wint + (size_t)DINNER * DMODEL, p_xresb + DINNER,
        TOK, 2 * DINNER, DMODEL, DMODEL, DMODEL, nullptr);
    cudaEventRecord(evJoin, s2);

    // 3) conv + silu (x half only)
    conv_silu_kernel<<<(TOK / 8 * DINNER) / 256, 256>>>(conv_w, conv_b);

    // 4) x_proj: split-K bf16 mma -> partials
    gemm_bf16<float><<<dim3(1, TOK / 128, XKSPLIT), 128, GEMM_SMEM>>>(
        p_xcb, p_wxt, p_xpf, TOK, XPAD, DINNER, DINNER, DINNER / XKSPLIT, nullptr);

    // 5) fused reduce + delta
    delta_fused_kernel<<<TOK / 16, 512>>>(W_dt, b_dt);

    // 6) chunked selective scan (A, B don't need res half)
    scanA_kernel<<<(BATCH * NCHUNK * DINNER) / 256, 256>>>(Amat);
    scanB_kernel<<<(BATCH * DN / 4) / 256, 256>>>();

    // join: scanC reads the res half
    cudaStreamWaitEvent(0, evJoin, 0);
    scanC_kernel<<<(BATCH * NCHUNK * DINNER) / 256, 256>>>(Amat, Dvec);

    // 7) out_proj (bf16 mma, fp32 out) + residual
    gemm_bf16<float><<<dim3(DMODEL / 128, TOK / 128), 128, GEMM_SMEM>>>(
        p_yb, p_woutt, out, TOK, DMODEL, DINNER, DINNER, DINNER, x0);
}